// round 13
// baseline (speedup 1.0000x reference)
#include <cuda_runtime.h>
#include <cuda_fp16.h>
#include <math.h>
#include <stdint.h>

#define LQ      1024
#define BATCH   2
#define DMODEL  1024
#define NH      16
#define DHD     64
#define MEMLEN  1024
#define TT      2048
#define NG      (BATCH*NH)
#define SCALE_F 0.125f
#define EXPC    8.0f
#define SROW    72          // halves per staged row
#define SROWB   144         // bytes per staged row
#define BDS     132         // floats per BD strip row

// ---------------- scratch -------------------------------------------------------
__device__ __half g_q [NG*LQ*DHD];
__device__ __half g_k [NG*TT*DHD];
__device__ __half g_v [NG*TT*DHD];
__device__ __half g_r [NG*TT*DHD];
__device__ __half g_p [(size_t)NG*LQ*TT];            // unnormalized e^(s-8) (fp16)
__device__ float  g_rs[NG*LQ];                       // row sums of e^(s-8)
__device__ __half g_av[LQ*BATCH*NH*DHD];
__device__ float  g_h [LQ*BATCH*DMODEL];
// fp16 pre-converted weights
__device__ __half   g_wqt  [1024*1024];              // W^T [n][k] fp16
__device__ __half   g_wkvt [2048*1024];
__device__ __half   g_wrelt[1024*1024];
__device__ unsigned g_woi  [512*1024];               // (W[2k],W[2k+1]) half2 pairs (wo)

// ---------------- helpers ---------------------------------------------------------
__device__ __forceinline__ unsigned pack_h2(float a, float b){
    __half2 h = __floats2half2_rn(a, b);
    return *reinterpret_cast<unsigned*>(&h);
}
__device__ __forceinline__ void mma_f16(float c[4],
                                        unsigned a0, unsigned a1, unsigned a2, unsigned a3,
                                        unsigned b0, unsigned b1){
    asm volatile("mma.sync.aligned.m16n8k16.row.col.f32.f16.f16.f32 "
        "{%0,%1,%2,%3}, {%4,%5,%6,%7}, {%8,%9}, {%0,%1,%2,%3};"
        : "+f"(c[0]), "+f"(c[1]), "+f"(c[2]), "+f"(c[3])
        : "r"(a0), "r"(a1), "r"(a2), "r"(a3), "r"(b0), "r"(b1));
}
__device__ __forceinline__ unsigned smem_u32(const void* p){
    return (unsigned)__cvta_generic_to_shared(p);
}
__device__ __forceinline__ void ldsm4(unsigned &r0, unsigned &r1, unsigned &r2, unsigned &r3, unsigned a){
    asm volatile("ldmatrix.sync.aligned.m8n8.x4.shared.b16 {%0,%1,%2,%3}, [%4];"
        : "=r"(r0),"=r"(r1),"=r"(r2),"=r"(r3) : "r"(a));
}
__device__ __forceinline__ void ldsm4t(unsigned &r0, unsigned &r1, unsigned &r2, unsigned &r3, unsigned a){
    asm volatile("ldmatrix.sync.aligned.m8n8.x4.trans.shared.b16 {%0,%1,%2,%3}, [%4];"
        : "=r"(r0),"=r"(r1),"=r"(r2),"=r"(r3) : "r"(a));
}

__device__ __forceinline__ float blockSum(float v){
    __shared__ float sm[32];
    int lane = threadIdx.x & 31, w = threadIdx.x >> 5;
    #pragma unroll
    for (int o=16;o>0;o>>=1) v += __shfl_xor_sync(0xffffffffu, v, o);
    if (lane==0) sm[w] = v;
    __syncthreads();
    float r = (threadIdx.x < 8) ? sm[threadIdx.x] : 0.f;
    if (w==0){
        #pragma unroll
        for (int o=4;o>0;o>>=1) r += __shfl_xor_sync(0xffffffffu, r, o);
        if (lane==0) sm[0]=r;
    }
    __syncthreads();
    r = sm[0];
    __syncthreads();
    return r;
}

// ---------------- fp16 weight pre-conversion --------------------------------------
__device__ __forceinline__ void cvt_inter(const float* __restrict__ W, unsigned* d,
                                          int b, int t, int lgN){
    const int p = b*1024 + t*4;
    const int N = 1 << lgN;
    const int k2 = p >> lgN, n = p & (N-1);
    const float* r0 = W + ((size_t)k2*2)*N + n;
    float4 a = *(const float4*)r0;
    float4 c = *(const float4*)(r0 + N);
    unsigned u[4] = { pack_h2(a.x,c.x), pack_h2(a.y,c.y),
                      pack_h2(a.z,c.z), pack_h2(a.w,c.w) };
    *(uint4*)&d[p] = *(uint4*)u;
}
// transpose 64x64 tile of W[1024][N] fp32 -> Wt[N][1024] fp16
__device__ void cvt_wt_tile(const float* __restrict__ W, __half* Wt, int N,
                            int ky, int nx, int tid){
    __shared__ float buf[64][65];
    const int k0 = ky*64, n0c = nx*64;
    const int kr = tid>>2, nc = (tid&3)*16;
    #pragma unroll
    for (int q=0;q<4;q++){
        float4 w = *(const float4*)(W + (size_t)(k0+kr)*N + n0c + nc + q*4);
        buf[kr][nc+q*4+0]=w.x; buf[kr][nc+q*4+1]=w.y;
        buf[kr][nc+q*4+2]=w.z; buf[kr][nc+q*4+3]=w.w;
    }
    __syncthreads();
    const int nr = tid>>2, kc = (tid&3)*16;
    unsigned u[8];
    #pragma unroll
    for (int e=0;e<8;e++)
        u[e] = pack_h2(buf[kc+2*e][nr], buf[kc+2*e+1][nr]);
    __half* dst = Wt + (size_t)(n0c+nr)*1024 + k0 + kc;
    *(uint4*)dst     = *(uint4*)&u[0];
    *(uint4*)(dst+8) = *(uint4*)&u[4];
}
__global__ __launch_bounds__(256) void cvt_all(const float* __restrict__ Wq,
                                               const float* __restrict__ Wkv,
                                               const float* __restrict__ Wrel,
                                               const float* __restrict__ Wo)
{
    const int bid = blockIdx.x, tid = threadIdx.x;
    if (bid < 512) cvt_inter(Wo, g_woi, bid, tid, 10);
    else {
        int t = bid - 512;
        if (t < 256)      cvt_wt_tile(Wq,   g_wqt,   1024, t>>4,        t&15,        tid);
        else if (t < 768) cvt_wt_tile(Wkv,  g_wkvt,  2048, (t-256)>>5,  (t-256)&31,  tid);
        else              cvt_wt_tile(Wrel, g_wrelt, 1024, (t-768)>>4,  (t-768)&15,  tid);
    }
}

// ---------------- QKVR projection GEMM (fp16 MMA, ping-pong, cp.async B) ---------
// C[m][n] = A_fp32[m][k] . Wt_fp16[n][k]; 128x128 tiles, 16 K-chunks of 64.
#define QK_SMEM_BYTES (4*128*SROW*2)   // 73728 B: As0,As1,Bs0,Bs1

__device__ __forceinline__ void qkvr_store(int mode, int row, int col, unsigned hv){
    const int t = row >> 1, bb = row & 1;
    if (mode==0){
        int h = col >> 6, d = col & 63;
        *reinterpret_cast<unsigned*>(&g_q[(((size_t)(bb*NH+h)*LQ + t)<<6) + d]) = hv;
    } else if (mode==1){
        int c2 = col; __half* dst = g_k;
        if (c2 >= NH*DHD){ dst = g_v; c2 -= NH*DHD; }
        int h = c2 >> 6, d = c2 & 63;
        *reinterpret_cast<unsigned*>(&dst[(((size_t)(bb*NH+h)*TT + t)<<6) + d]) = hv;
    } else {
        int h = col >> 6, d = col & 63;
        *reinterpret_cast<unsigned*>(&g_r[(((size_t)(bb*NH+h)*TT + t)<<6) + d]) = hv;
    }
}

__global__ void __launch_bounds__(256,2) qkvr_mma(const float* __restrict__ x,
                                                  const float* __restrict__ memory,
                                                  const float* __restrict__ pos_emb)
{
    extern __shared__ __half smqk[];
    __half* Asb[2] = { smqk,              smqk +   128*SROW };
    __half* Bsb[2] = { smqk + 2*128*SROW, smqk + 3*128*SROW };

    int bid = blockIdx.x;
    int mode, m0, n0;
    const __half* Wt;
    if (bid < 128)      { mode=0; m0=(bid>>3)<<7;  n0=(bid&7)<<7;  Wt=g_wqt;  }
    else if (bid < 640) { int t=bid-128; mode=1; m0=(t>>4)<<7; n0=(t&15)<<7; Wt=g_wkvt; }
    else                { int t=bid-640; mode=2; m0=(t>>3)<<7; n0=(t&7)<<7;  Wt=g_wrelt;}

    const int tid = threadIdx.x;
    const int warp = tid >> 5, lane = tid & 31;
    const int gq = lane >> 2, tq = lane & 3;
    const int sel = lane >> 3, l7 = lane & 7;
    const int wm = warp << 4;

    const unsigned offA = (((sel&1)*8 + l7)*SROW + (sel>>1)*8)*2;
    const unsigned offB = (((sel>>1)*8 + l7)*SROW + (sel&1)*8)*2;
    unsigned asA[2], bsB[2], bdst[2];
    const int sr = tid >> 1, cb = (tid & 1) * 32;
    #pragma unroll
    for (int s=0;s<2;s++){
        asA[s] = smem_u32(Asb[s]) + wm*SROWB + offA;
        bsB[s] = smem_u32(Bsb[s]) + offB;
        bdst[s] = smem_u32(Bsb[s]) + (sr*SROW + cb)*2;
    }

    const float* arow;
    {
        int grow = m0 + sr;
        if (mode==0)      arow = x + (size_t)grow*DMODEL;
        else if (mode==1) arow = (grow < MEMLEN*BATCH) ? memory + (size_t)grow*DMODEL
                                                       : x + (size_t)(grow - MEMLEN*BATCH)*DMODEL;
        else              arow = pos_emb + (size_t)grow*DMODEL;
    }
    const __half* brow = Wt + (size_t)(n0 + sr)*DMODEL;

    // prologue: stage chunk 0
    #pragma unroll
    for (int q=0;q<4;q++){
        float4 fa = *(const float4*)(arow + cb + q*8);
        float4 fb = *(const float4*)(arow + cb + q*8 + 4);
        unsigned u[4] = { pack_h2(fa.x,fa.y), pack_h2(fa.z,fa.w),
                          pack_h2(fb.x,fb.y), pack_h2(fb.z,fb.w) };
        *(uint4*)&Asb[0][sr*SROW + cb + q*8] = *(uint4*)u;
        asm volatile("cp.async.cg.shared.global [%0], [%1], 16;"
            :: "r"(bdst[0] + q*16), "l"(brow + cb + q*8));
    }
    asm volatile("cp.async.commit_group;");
    asm volatile("cp.async.wait_group 0;");
    __syncthreads();

    float acc[16][4];
    #pragma unroll
    for (int ni=0;ni<16;ni++)
        #pragma unroll
        for (int c=0;c<4;c++) acc[ni][c]=0.f;

    for (int c=0;c<16;c++){
        const int s = c & 1;
        float4 pre[8];
        if (c < 15){
            const float* asrc = arow + (c+1)*64 + cb;
            #pragma unroll
            for (int q=0;q<8;q++) pre[q] = *(const float4*)(asrc + q*4);
            const __half* bsrc = brow + (c+1)*64 + cb;
            #pragma unroll
            for (int q=0;q<4;q++)
                asm volatile("cp.async.cg.shared.global [%0], [%1], 16;"
                    :: "r"(bdst[s^1] + q*16), "l"(bsrc + q*8));
            asm volatile("cp.async.commit_group;");
        }
        #pragma unroll
        for (int kk=0;kk<64;kk+=16){
            unsigned a0,a1,a2,a3;
            ldsm4(a0,a1,a2,a3, asA[s] + kk*2);
            #pragma unroll
            for (int q=0;q<8;q++){
                unsigned b0,b1,b2,b3;
                ldsm4(b0,b1,b2,b3, bsB[s] + q*2304 + kk*2);
                mma_f16(acc[2*q  ], a0,a1,a2,a3, b0,b1);
                mma_f16(acc[2*q+1], a0,a1,a2,a3, b2,b3);
            }
        }
        if (c < 15){
            #pragma unroll
            for (int q=0;q<4;q++){
                unsigned u[4] = { pack_h2(pre[2*q].x,  pre[2*q].y),
                                  pack_h2(pre[2*q].z,  pre[2*q].w),
                                  pack_h2(pre[2*q+1].x,pre[2*q+1].y),
                                  pack_h2(pre[2*q+1].z,pre[2*q+1].w) };
                *(uint4*)&Asb[s^1][sr*SROW + cb + q*8] = *(uint4*)u;
            }
            asm volatile("cp.async.wait_group 0;");
        }
        __syncthreads();
    }

    const int row0 = m0 + wm + gq, row1 = row0 + 8;
    #pragma unroll
    for (int ni=0;ni<16;ni++){
        const int col = n0 + ni*8 + 2*tq;
        qkvr_store(mode, row0, col, pack_h2(acc[ni][0], acc[ni][1]));
        qkvr_store(mode, row1, col, pack_h2(acc[ni][2], acc[ni][3]));
    }
}

// ---------------- BD strip: BDslot[128][132] = Q . Rs^T + vR (folded) ------------
__device__ __forceinline__ void compute_strip(unsigned qs_u32, unsigned rs_u32,
                                              float* BDslot, const float* vRslot,
                                              int warp, int lane)
{
    const int sel = lane >> 3, l7 = lane & 7;
    const int gq = lane >> 2, tq = lane & 3;
    const int wmb = (warp >> 1) * 32, wnb = (warp & 1) * 64;
    const unsigned offA = (((sel&1)*8 + l7)*SROW + (sel>>1)*8)*2;
    const unsigned offB = (((sel>>1)*8 + l7)*SROW + (sel&1)*8)*2;

    float abd[2][2][4][4];
    #pragma unroll
    for (int pass=0; pass<2; pass++){
        #pragma unroll
        for (int mi=0;mi<2;mi++)
            #pragma unroll
            for (int ni=0;ni<4;ni++)
                #pragma unroll
                for (int e=0;e<4;e++) abd[pass][mi][ni][e]=0.f;
        #pragma unroll
        for (int kk=0;kk<64;kk+=16){
            unsigned am[2][4];
            #pragma unroll
            for (int mi=0;mi<2;mi++)
                ldsm4(am[mi][0],am[mi][1],am[mi][2],am[mi][3],
                      qs_u32 + (wmb + mi*16)*SROWB + offA + kk*2);
            #pragma unroll
            for (int q=0;q<2;q++){
                unsigned b0,b1,b2,b3;
                ldsm4(b0,b1,b2,b3,
                      rs_u32 + (wnb + pass*32 + 16*q)*SROWB + offB + kk*2);
                mma_f16(abd[pass][0][2*q  ], am[0][0],am[0][1],am[0][2],am[0][3], b0,b1);
                mma_f16(abd[pass][0][2*q+1], am[0][0],am[0][1],am[0][2],am[0][3], b2,b3);
                mma_f16(abd[pass][1][2*q  ], am[1][0],am[1][1],am[1][2],am[1][3], b0,b1);
                mma_f16(abd[pass][1][2*q+1], am[1][0],am[1][1],am[1][2],am[1][3], b2,b3);
            }
        }
    }
    __syncthreads();   // vRslot writes (pre-call, program order) visible to all
    #pragma unroll
    for (int pass=0; pass<2; pass++)
        #pragma unroll
        for (int mi=0;mi<2;mi++)
            #pragma unroll
            for (int rr=0;rr<2;rr++){
                const int il = wmb + mi*16 + gq + rr*8;
                #pragma unroll
                for (int ni=0;ni<4;ni++){
                    const int pl = wnb + pass*32 + ni*8 + 2*tq;
                    float2 v = { abd[pass][mi][ni][rr*2+0] + vRslot[pl],
                                 abd[pass][mi][ni][rr*2+1] + vRslot[pl+1] };
                    *(float2*)&BDslot[il*BDS + pl] = v;
                }
            }
}

// ---------------- flash: scores (AC + strip-shared BD) + exp + PV ----------------
#define FL_SMEM_BYTES 210944
__global__ __launch_bounds__(256) void flash_mma(const float* __restrict__ ubias,
                                                 const float* __restrict__ vbias)
{
    const int gg = blockIdx.y, h = gg & (NH-1);
    const int bi = 7 - blockIdx.x;            // heavy CTAs first
    const int i0 = bi << 7;

    extern __shared__ char smr[];
    __half* Qs = (__half*)smr;                 // [128][72]
    __half* Ks = (__half*)(smr + 18432);       // [128][72]
    __half* Rs = (__half*)(smr + 36864);       // [128][72]
    __half* Vs = (__half*)(smr + 55296);       // [128 t][72 d]
    float*  BD0 = (float*)(smr + 73728);       // [128][132]
    float*  BD1 = (float*)(smr + 141312);
    float*  uKs = (float*)(smr + 208896);      // [128]
    float*  vR0 = (float*)(smr + 209408);      // [128]
    float*  vR1 = (float*)(smr + 209920);
    float*  u_s = (float*)(smr + 210432);      // [64]
    float*  v_s = (float*)(smr + 210688);

    const int tid = threadIdx.x;
    const int warp = tid >> 5, lane = tid & 31;
    const int gq = lane >> 2, tq = lane & 3;
    const int sel = lane >> 3, l7 = lane & 7;
    const int wm = warp << 4;                  // 16 AC rows per warp

    const unsigned qs_u32 = smem_u32(Qs);
    const unsigned ks_u32 = smem_u32(Ks);
    const unsigned rs_u32 = smem_u32(Rs);
    const unsigned vs_u32 = smem_u32(Vs);
    const unsigned offA = (((sel&1)*8 + l7)*SROW + (sel>>1)*8)*2;
    const unsigned offB = (((sel>>1)*8 + l7)*SROW + (sel&1)*8)*2;
    const unsigned qsA = qs_u32 + wm*SROWB + offA;
    const unsigned ksB = ks_u32 + offB;
    const unsigned vsB = vs_u32 + offA;

    const int sr = tid >> 1, cb = (tid & 1) * 32;

    // ---- prologue: stage Q, biases, strip 0 ----
    {
        const __half* qrow = g_q + (((size_t)gg*LQ + i0 + sr) << 6) + cb;
        #pragma unroll
        for (int q=0;q<4;q++)
            *(uint4*)&Qs[sr*SROW + cb + q*8] = *(const uint4*)(qrow + q*8);
        if (tid < 64)       u_s[tid]    = ubias[(h<<6) + tid];
        else if (tid < 128) v_s[tid-64] = vbias[(h<<6) + tid - 64];
        const int ps0 = (7 - bi) << 7;
        const __half* rrow = g_r + (((size_t)gg*TT + ps0 + sr) << 6) + cb;
        #pragma unroll
        for (int q=0;q<4;q++)
            *(uint4*)&Rs[sr*SROW + cb + q*8] = *(const uint4*)(rrow + q*8);
    }
    __syncthreads();
    if (tid >= 128){
        const int c = tid - 128;
        float s = 0.f;
        #pragma unroll
        for (int d=0;d<64;d++) s += v_s[d] * __half2float(Rs[c*SROW + d]);
        vR0[c] = s;
    }
    compute_strip(qs_u32, rs_u32, BD0, vR0, warp, lane);

    float acc_pv[8][4];
    #pragma unroll
    for (int ni=0;ni<8;ni++)
        #pragma unroll
        for (int c=0;c<4;c++) acc_pv[ni][c]=0.f;
    float rs_0 = 0.f, rs_1 = 0.f;

    const int jt_max = bi + 8;
    for (int jt=0; jt<=jt_max; jt++){
        const int j0 = jt << 7;
        const bool doStrip = (jt < jt_max);
        __syncthreads();                       // S1
        // stage K, V (and R for strip jt+1)
        {
            const __half* krow = g_k + (((size_t)gg*TT + j0 + sr) << 6) + cb;
            const __half* vrow = g_v + (((size_t)gg*TT + j0 + sr) << 6) + cb;
            #pragma unroll
            for (int q=0;q<4;q++){
                *(uint4*)&Ks[sr*SROW + cb + q*8] = *(const uint4*)(krow + q*8);
                *(uint4*)&Vs[sr*SROW + cb + q*8] = *(const uint4*)(vrow + q*8);
            }
            if (doStrip){
                const int ps = (jt + 1 - bi + 7) << 7;
                const __half* rrow = g_r + (((size_t)gg*TT + ps + sr) << 6) + cb;
                #pragma unroll
                for (int q=0;q<4;q++)
                    *(uint4*)&Rs[sr*SROW + cb + q*8] = *(const uint4*)(rrow + q*8);
            }
        }
        __syncthreads();                       // S2
        if (tid < 128){
            float s = 0.f;
            #pragma unroll
            for (int d=0;d<64;d++) s += u_s[d] * __half2float(Ks[tid*SROW + d]);
            uKs[tid] = s;
        } else if (doStrip){
            const int c = tid - 128;
            float s = 0.f;
            #pragma unroll
            for (int d=0;d<64;d++) s += v_s[d] * __half2float(Rs[c*SROW + d]);
            (((jt+1)&1) ? vR1 : vR0)[c] = s;
        }
        // AC = Q.K^T (warp tile 16x128) via ldmatrix
        float acc[16][4];
        #pragma unroll
        for (int ni=0;ni<16;ni++)
            #pragma unroll
            for (int c=0;c<4;c++) acc[ni][c]=0.f;
        #pragma unroll
        for (int kk=0;kk<64;kk+=16){
            unsigned a0,a1,a2,a3;
            ldsm4(a0,a1,a2,a3, qsA + kk*2);
            #pragma unroll
            for (int q=0;q<8;q++){
                unsigned b0,b1,b2,b3;
                ldsm4(b0,b1,b2,b3, ksB + q*2304 + kk*2);
                mma_f16(acc[2*q  ], a0,a1,a2,a3, b0,b1);
                mma_f16(acc[2*q+1], a0,a1,a2,a3, b2,b3);
            }
        }
        if (doStrip)
            compute_strip(qs_u32, rs_u32, ((jt+1)&1) ? BD1 : BD0,
                          ((jt+1)&1) ? vR1 : vR0, warp, lane);
        __syncthreads();                       // S3
        // gather + exp + mask + write p + row sums
        const bool isDiag = (jt == jt_max);
        const float* BDa = (jt & 1) ? BD1 : BD0;
        const float* BDb = (jt & 1) ? BD0 : BD1;
        const int il0 = wm + gq, il1 = il0 + 8;
        unsigned pfrag[16][2];
        __half* prow0 = g_p + ((size_t)gg*LQ + i0 + il0)*TT + j0;
        __half* prow1 = g_p + ((size_t)gg*LQ + i0 + il1)*TT + j0;
        #pragma unroll
        for (int ni=0;ni<16;ni++){
            const int jl = ni*8 + 2*tq;
            const int o00 = jl - il0 + 127;
            const int o10 = jl - il1 + 127;
            float bd00 = (o00   < 128) ? BDa[il0*BDS + o00    ] : BDb[il0*BDS + o00-128];
            float bd01 = (o00+1 < 128) ? BDa[il0*BDS + o00 + 1] : BDb[il0*BDS + o00-127];
            float bd10 = (o10   < 128) ? BDa[il1*BDS + o10    ] : BDb[il1*BDS + o10-128];
            float bd11 = (o10+1 < 128) ? BDa[il1*BDS + o10 + 1] : BDb[il1*BDS + o10-127];
            const float u0 = uKs[jl], u1 = uKs[jl+1];
            float p0 = __expf((acc[ni][0] + bd00 + u0)*SCALE_F - EXPC);
            float p1 = __expf((acc[ni][1] + bd01 + u1)*SCALE_F - EXPC);
            float p2 = __expf((acc[ni][2] + bd10 + u0)*SCALE_F - EXPC);
            float p3 = __expf((acc[ni][3] + bd11 + u1)*SCALE_F - EXPC);
            if (isDiag){
                if (jl   > il0) p0 = 0.f;
                if (jl+1 > il0) p1 = 0.f;
                if (jl   > il1) p2 = 0.f;
                if (jl+1 > il1) p3 = 0.f;
            }
            rs_0 += p0 + p1;
            rs_1 += p2 + p3;
            unsigned lo = pack_h2(p0, p1), hi = pack_h2(p2, p3);
            *reinterpret_cast<unsigned*>(prow0 + jl) = lo;
            *reinterpret_cast<unsigned*>(prow1 + jl) = hi;
            pfrag[ni][0] = lo;
            pfrag[ni][1] = hi;
        }
        // PV: acc_pv += P(tile) @ V(tile), V frags via ldmatrix.trans
        #pragma unroll
        for (int s=0;s<8;s++){
            unsigned a0 = pfrag[2*s][0], a1 = pfrag[2*s][1];
            unsigned a2 = pfrag[2*s+1][0], a3 = pfrag[2*s+1][1];
            #pragma unroll
            for (int q=0;q<4;q++){
                unsigned b0,b1,b2,b3;
                ldsm4t(b0,b1,b2,b3, vsB + s*2304 + q*32);
                mma_f16(acc_pv[2*q  ], a0,a1,a2,a3, b0,b1);
                mma_f16(acc_pv[2*q+1], a0,a1,a2,a3, b2,b3);
            }
        }
    }

    // epilogue: row sums, normalize, write av
    rs_0 += __shfl_xor_sync(0xffffffffu, rs_0, 1);
    rs_0 += __shfl_xor_sync(0xffffffffu, rs_0, 2);
    rs_1 += __shfl_xor_sync(0xffffffffu, rs_1, 1);
    rs_1 += __shfl_xor_sync(0xffffffffu, rs_1, 2);
    const int row0 = i0 + wm + gq, row1 = row0 + 8;
    if (tq == 0){
        g_rs[gg*LQ + row0] = rs_0;
        g_rs[gg*LQ + row1] = rs_1;
    }
    const float inv0 = 1.f / rs_0, inv1 = 1.f / rs_1;
    const int b = gg >> 4;
    __half* dst0 = g_av + (size_t)(row0*BATCH + b)*DMODEL + (h<<6);
    __half* dst1 = g_av + (size_t)(row1*BATCH + b)*DMODEL + (h<<6);
    #pragma unroll
    for (int ni=0;ni<8;ni++){
        const int d = ni*8 + 2*tq;
        *reinterpret_cast<unsigned*>(dst0 + d) = pack_h2(acc_pv[ni][0]*inv0, acc_pv[ni][1]*inv0);
        *reinterpret_cast<unsigned*>(dst1 + d) = pack_h2(acc_pv[ni][2]*inv1, acc_pv[ni][3]*inv1);
    }
}

// ---------------- attn_matrix = mean over (b,h) of p/rs --------------------------
__global__ __launch_bounds__(256) void attnmat_kernel(float* __restrict__ out)
{
    const int i  = blockIdx.y;
    const int j0 = blockIdx.x << 9;            // 4 tiles of 512
    const int jmax = i + MEMLEN;
    const int tid = threadIdx.x;
    const int jq = tid & 63;
    const int gsel = tid >> 6;
    const int j = j0 + jq*8;
    __shared__ float red[256][9];

    float a[8] = {0.f,0.f,0.f,0.f,0.f,0.f,0.f,0.f};
    if (j0 <= jmax){
        #pragma unroll
        for (int gi=0; gi<8; gi++){
            int g = gsel*8 + gi;
            float inv = 1.f / g_rs[g*LQ + i];
            uint4 raw = *(const uint4*)(g_p + ((size_t)g*LQ + i)*TT + j);
            const __half2* hp = (const __half2*)&raw;
            #pragma unroll
            for (int e=0;e<4;e++){
                float2 f = __half22float2(hp[e]);
                a[2*e]   += f.x * inv;
                a[2*e+1] += f.y * inv;
            }
        }
        #pragma unroll
        for (int e=0;e<8;e++) if (j+e > jmax) a[e] = 0.f;
    }
    #pragma unroll
    for (int e=0;e<8;e++) red[tid][e] = a[e];
    __syncthreads();
    if (tid < 64){
        const float k = 1.f/NG;
        float o[8];
        #pragma unroll
        for (int e=0;e<8;e++)
            o[e] = (red[tid][e] + red[tid+64][e] + red[tid+128][e] + red[tid+192][e]) * k;
        float* dst = out + (size_t)i*TT + j0 + tid*8;
        *(float4*)dst     = make_float4(o[0],o[1],o[2],o[3]);
        *(float4*)(dst+4) = make_float4(o[4],o[5],o[6],o[7]);
    }
}

// ---------------- Wo GEMM + residual (fp16 MMA): g_h = x + g_av @ Wo ------------
__global__ __launch_bounds__(256) void wo_mma(const float* __restrict__ x)
{
    const int m0 = blockIdx.y << 7;
    const int n0 = blockIdx.x << 6;

    __shared__ __half   As[128*40];
    __shared__ unsigned Bs[16*72];

    const int tid = threadIdx.x;
    const int warp = tid >> 5, lane = tid & 31;
    const int gq = lane >> 2, tq = lane & 3;
    const int wm = (warp >> 1) * 32, wn = (warp & 1) * 32;
    const unsigned* As2 = (const unsigned*)As;

    float acc[2][4][4];
    #pragma unroll
    for (int mi=0;mi<2;mi++)
        #pragma unroll
        for (int ni=0;ni<4;ni++)
            #pragma unroll
            for (int c=0;c<4;c++) acc[mi][ni][c]=0.f;

    const int a_r = tid >> 1;
    const int a_cb = (tid & 1) * 16;
    const __half* arow = g_av + (size_t)(m0 + a_r)*DMODEL + a_cb;
    const int b_k2 = tid >> 4;
    const int b_cb = (tid & 15) * 4;

    for (int k0=0;k0<DMODEL;k0+=32){
        {
            __half* Ad = As + a_r*40 + a_cb;
            *(uint4*)Ad     = *(const uint4*)(arow + k0);
            *(uint4*)(Ad+8) = *(const uint4*)(arow + k0 + 8);
            const unsigned* bsrc = g_woi + (size_t)((k0>>1) + b_k2)*DMODEL + n0 + b_cb;
            *(uint4*)&Bs[b_k2*72 + b_cb] = *(const uint4*)bsrc;
        }
        __syncthreads();
        #pragma unroll
        for (int kk=0;kk<32;kk+=16){
            const int k2 = kk >> 1;
            unsigned a[2][4], bfr[4][2];
            #pragma unroll
            for (int mi=0;mi<2;mi++){
                int m = wm + mi*16;
                a[mi][0] = As2[(m+gq  )*20 + k2 + tq  ];
                a[mi][1] = As2[(m+gq+8)*20 + k2 + tq  ];
                a[mi][2] = As2[(m+gq  )*20 + k2 + tq+4];
                a[mi][3] = As2[(m+gq+8)*20 + k2 + tq+4];
            }
            #pragma unroll
            for (int ni=0;ni<4;ni++){
                int n = wn + ni*8 + gq;
                bfr[ni][0] = Bs[(k2+tq  )*72 + n];
                bfr[ni][1] = Bs[(k2+tq+4)*72 + n];
            }
            #pragma unroll
            for (int mi=0;mi<2;mi++)
                #pragma unroll
                for (int ni=0;ni<4;ni++)
                    mma_f16(acc[mi][ni], a[mi][0],a[mi][1],a[mi][2],a[mi][3], bfr[ni][0],bfr[ni][1]);
        }
        __syncthreads();
    }

    #pragma unroll
    for (int mi=0;mi<2;mi++)
        #pragma unroll
        for (int rr=0;rr<2;rr++){
            const int row = m0 + wm + mi*16 + gq + rr*8;
            #pragma unroll
            for (int ni=0;ni<4;ni++){
                const int col = n0 + wn + ni*8 + 2*tq;
                float2 xv = *(const float2*)&x[(size_t)row*DMODEL + col];
                float2 val = { acc[mi][ni][rr*2+0] + xv.x,
                               acc[mi][ni][rr*2+1] + xv.y };
                *(float2*)&g_h[(size_t)row*DMODEL + col] = val;
            }
        }
}

// ---------------- layernorm ------------------------------------------------------
__global__ __launch_bounds__(256) void ln_kernel(const float* __restrict__ gamma,
                                                 const float* __restrict__ beta,
                                                 float* __restrict__ out)
{
    const int row = blockIdx.x;
    const float* hr = g_h + (size_t)row*DMODEL;
    const int c = threadIdx.x * 4;
    float4 v = *(const float4*)(hr + c);
    float s = v.x+v.y+v.z+v.w;
    s = blockSum(s);
    const float mu = s * (1.f/DMODEL);
    float dx = v.x-mu, dy = v.y-mu, dz = v.z-mu, dw = v.w-mu;
    float sq = dx*dx+dy*dy+dz*dz+dw*dw;
    sq = blockSum(sq);
    const float inv = rsqrtf(sq*(1.f/DMODEL) + 1e-5f);
    float4 gm = *(const float4*)(gamma + c);
    float4 bt = *(const float4*)(beta + c);
    float4 o;
    o.x = dx*inv*gm.x + bt.x;
    o.y = dy*inv*gm.y + bt.y;
    o.z = dz*inv*gm.z + bt.z;
    o.w = dw*inv*gm.w + bt.w;
    *(float4*)(out + (size_t)row*DMODEL + c) = o;
}

// ---------------- launch ----------------------------------------------------------
extern "C" void kernel_launch(void* const* d_in, const int* in_sizes, int n_in,
                              void* d_out, int out_size)
{
    const float* x        = (const float*)d_in[0];
    const float* pos_emb  = (const float*)d_in[1];
    const float* memory   = (const float*)d_in[2];
    const float* ubias    = (const float*)d_in[3];
    const float* vbias    = (const float*)d_in[4];
    const float* Wq       = (const float*)d_in[6];
    const float* Wkv      = (const float*)d_in[7];
    const float* Wrel     = (const float*)d_in[8];
    const float* Wo       = (const float*)d_in[9];
    const float* gamma    = (const float*)d_in[10];
    const float* beta     = (const float*)d_in[11];
    float* out    = (float*)d_out;
    float* out_am = out + (size_t)LQ*BATCH*DMODEL;

    cudaFuncSetAttribute(flash_mma, cudaFuncAttributeMaxDynamicSharedMemorySize, FL_SMEM_BYTES);
    cudaFuncSetAttribute(qkvr_mma,  cudaFuncAttributeMaxDynamicSharedMemorySize, QK_SMEM_BYTES);

    cvt_all<<<1536, 256>>>(Wq, Wkv, Wrel, Wo);
    qkvr_mma<<<896, 256, QK_SMEM_BYTES>>>(x, memory, pos_emb);
    flash_mma<<<dim3(8, NG), 256, FL_SMEM_BYTES>>>(ubias, vbias);
    attnmat_kernel<<<dim3(4, LQ), 256>>>(out_am);
    wo_mma<<<dim3(16,16), 256>>>(x);
    ln_kernel<<<LQ*BATCH, 256>>>(gamma, beta, out);
}

// round 14
// speedup vs baseline: 1.1686x; 1.1686x over previous
#include <cuda_runtime.h>
#include <cuda_fp16.h>
#include <math.h>
#include <stdint.h>

#define LQ      1024
#define BATCH   2
#define DMODEL  1024
#define NH      16
#define DHD     64
#define MEMLEN  1024
#define TT      2048
#define NG      (BATCH*NH)
#define SCALE_F 0.125f
#define EXPC    8.0f
#define SROW    72          // halves per staged row
#define SROWB   144         // bytes per staged row
#define BDS     132         // floats per BD strip row

// ---------------- scratch -------------------------------------------------------
__device__ __half g_q [NG*LQ*DHD];
__device__ __half g_k [NG*TT*DHD];
__device__ __half g_v [NG*TT*DHD];
__device__ __half g_r [NG*TT*DHD];
__device__ __half g_p [(size_t)NG*LQ*TT];            // unnormalized e^(s-8) (fp16)
__device__ float  g_rs[NG*LQ];                       // row sums of e^(s-8)
__device__ __half g_av[LQ*BATCH*NH*DHD];
__device__ float  g_h [LQ*BATCH*DMODEL];
// fp16 pre-converted inputs / weights
__device__ __half   g_xh   [LQ*BATCH*DMODEL];
__device__ __half   g_memh [MEMLEN*BATCH*DMODEL];
__device__ __half   g_posh [TT*BATCH*DMODEL];
__device__ __half   g_wqt  [1024*1024];              // W^T [n][k] fp16
__device__ __half   g_wkvt [2048*1024];
__device__ __half   g_wrelt[1024*1024];
__device__ unsigned g_woi  [512*1024];               // (W[2k],W[2k+1]) half2 pairs (wo)

// ---------------- helpers ---------------------------------------------------------
__device__ __forceinline__ unsigned pack_h2(float a, float b){
    __half2 h = __floats2half2_rn(a, b);
    return *reinterpret_cast<unsigned*>(&h);
}
__device__ __forceinline__ void mma_f16(float c[4],
                                        unsigned a0, unsigned a1, unsigned a2, unsigned a3,
                                        unsigned b0, unsigned b1){
    asm volatile("mma.sync.aligned.m16n8k16.row.col.f32.f16.f16.f32 "
        "{%0,%1,%2,%3}, {%4,%5,%6,%7}, {%8,%9}, {%0,%1,%2,%3};"
        : "+f"(c[0]), "+f"(c[1]), "+f"(c[2]), "+f"(c[3])
        : "r"(a0), "r"(a1), "r"(a2), "r"(a3), "r"(b0), "r"(b1));
}
__device__ __forceinline__ unsigned smem_u32(const void* p){
    return (unsigned)__cvta_generic_to_shared(p);
}
__device__ __forceinline__ void ldsm4(unsigned &r0, unsigned &r1, unsigned &r2, unsigned &r3, unsigned a){
    asm volatile("ldmatrix.sync.aligned.m8n8.x4.shared.b16 {%0,%1,%2,%3}, [%4];"
        : "=r"(r0),"=r"(r1),"=r"(r2),"=r"(r3) : "r"(a));
}
__device__ __forceinline__ void ldsm4t(unsigned &r0, unsigned &r1, unsigned &r2, unsigned &r3, unsigned a){
    asm volatile("ldmatrix.sync.aligned.m8n8.x4.trans.shared.b16 {%0,%1,%2,%3}, [%4];"
        : "=r"(r0),"=r"(r1),"=r"(r2),"=r"(r3) : "r"(a));
}

__device__ __forceinline__ float blockSum(float v){
    __shared__ float sm[32];
    int lane = threadIdx.x & 31, w = threadIdx.x >> 5;
    #pragma unroll
    for (int o=16;o>0;o>>=1) v += __shfl_xor_sync(0xffffffffu, v, o);
    if (lane==0) sm[w] = v;
    __syncthreads();
    float r = (threadIdx.x < 8) ? sm[threadIdx.x] : 0.f;
    if (w==0){
        #pragma unroll
        for (int o=4;o>0;o>>=1) r += __shfl_xor_sync(0xffffffffu, r, o);
        if (lane==0) sm[0]=r;
    }
    __syncthreads();
    r = sm[0];
    __syncthreads();
    return r;
}

// ---------------- fp16 pre-conversion -------------------------------------------
__device__ __forceinline__ void cvt_plain(const float* __restrict__ s, __half* d, int b, int t){
    const int idx = b*2048 + t*8;
    float4 v0 = *(const float4*)(s+idx), v1 = *(const float4*)(s+idx+4);
    unsigned u[4] = { pack_h2(v0.x,v0.y), pack_h2(v0.z,v0.w),
                      pack_h2(v1.x,v1.y), pack_h2(v1.z,v1.w) };
    *(uint4*)&d[idx] = *(uint4*)u;
}
__device__ __forceinline__ void cvt_inter(const float* __restrict__ W, unsigned* d,
                                          int b, int t, int lgN){
    const int p = b*1024 + t*4;
    const int N = 1 << lgN;
    const int k2 = p >> lgN, n = p & (N-1);
    const float* r0 = W + ((size_t)k2*2)*N + n;
    float4 a = *(const float4*)r0;
    float4 c = *(const float4*)(r0 + N);
    unsigned u[4] = { pack_h2(a.x,c.x), pack_h2(a.y,c.y),
                      pack_h2(a.z,c.z), pack_h2(a.w,c.w) };
    *(uint4*)&d[p] = *(uint4*)u;
}
// transpose 64x64 tile of W[1024][N] fp32 -> Wt[N][1024] fp16
__device__ void cvt_wt_tile(const float* __restrict__ W, __half* Wt, int N,
                            int ky, int nx, int tid){
    __shared__ float buf[64][65];
    const int k0 = ky*64, n0c = nx*64;
    const int kr = tid>>2, nc = (tid&3)*16;
    #pragma unroll
    for (int q=0;q<4;q++){
        float4 w = *(const float4*)(W + (size_t)(k0+kr)*N + n0c + nc + q*4);
        buf[kr][nc+q*4+0]=w.x; buf[kr][nc+q*4+1]=w.y;
        buf[kr][nc+q*4+2]=w.z; buf[kr][nc+q*4+3]=w.w;
    }
    __syncthreads();
    const int nr = tid>>2, kc = (tid&3)*16;
    unsigned u[8];
    #pragma unroll
    for (int e=0;e<8;e++)
        u[e] = pack_h2(buf[kc+2*e][nr], buf[kc+2*e+1][nr]);
    __half* dst = Wt + (size_t)(n0c+nr)*1024 + k0 + kc;
    *(uint4*)dst     = *(uint4*)&u[0];
    *(uint4*)(dst+8) = *(uint4*)&u[4];
}
__global__ __launch_bounds__(256) void cvt_all(const float* __restrict__ x,
                                               const float* __restrict__ memory,
                                               const float* __restrict__ pos_emb,
                                               const float* __restrict__ Wq,
                                               const float* __restrict__ Wkv,
                                               const float* __restrict__ Wrel,
                                               const float* __restrict__ Wo)
{
    const int bid = blockIdx.x, tid = threadIdx.x;
    if      (bid < 1024) cvt_plain(x,       g_xh,   bid,        tid);
    else if (bid < 2048) cvt_plain(memory,  g_memh, bid-1024,   tid);
    else if (bid < 4096) cvt_plain(pos_emb, g_posh, bid-2048,   tid);
    else if (bid < 4608) cvt_inter(Wo, g_woi, bid-4096, tid, 10);
    else {
        int t = bid - 4608;
        if (t < 256)      cvt_wt_tile(Wq,   g_wqt,   1024, t>>4,        t&15,        tid);
        else if (t < 768) cvt_wt_tile(Wkv,  g_wkvt,  2048, (t-256)>>5,  (t-256)&31,  tid);
        else              cvt_wt_tile(Wrel, g_wrelt, 1024, (t-768)>>4,  (t-768)&15,  tid);
    }
}

// ---------------- QKVR projection GEMM (fp16 MMA, cp.async double-buffered) ------
// C[m][n] = A[m][k] . Wt[n][k]; 128x128 tiles, 16 K-chunks of 64.
#define QK_SMEM_BYTES (4*128*SROW*2)   // 73728 B: As0,As1,Bs0,Bs1

__device__ __forceinline__ void qkvr_store(int mode, int row, int col, unsigned hv){
    const int t = row >> 1, bb = row & 1;
    if (mode==0){
        int h = col >> 6, d = col & 63;
        *reinterpret_cast<unsigned*>(&g_q[(((size_t)(bb*NH+h)*LQ + t)<<6) + d]) = hv;
    } else if (mode==1){
        int c2 = col; __half* dst = g_k;
        if (c2 >= NH*DHD){ dst = g_v; c2 -= NH*DHD; }
        int h = c2 >> 6, d = c2 & 63;
        *reinterpret_cast<unsigned*>(&dst[(((size_t)(bb*NH+h)*TT + t)<<6) + d]) = hv;
    } else {
        int h = col >> 6, d = col & 63;
        *reinterpret_cast<unsigned*>(&g_r[(((size_t)(bb*NH+h)*TT + t)<<6) + d]) = hv;
    }
}

__global__ __launch_bounds__(256) void qkvr_mma()
{
    extern __shared__ __half smqk[];
    __half* Asb[2] = { smqk,              smqk +   128*SROW };
    __half* Bsb[2] = { smqk + 2*128*SROW, smqk + 3*128*SROW };

    int bid = blockIdx.x;
    int mode, m0, n0;
    const __half* Wt;
    if (bid < 128)      { mode=0; m0=(bid>>3)<<7;  n0=(bid&7)<<7;  Wt=g_wqt;  }
    else if (bid < 640) { int t=bid-128; mode=1; m0=(t>>4)<<7; n0=(t&15)<<7; Wt=g_wkvt; }
    else                { int t=bid-640; mode=2; m0=(t>>3)<<7; n0=(t&7)<<7;  Wt=g_wrelt;}

    const int tid = threadIdx.x;
    const int warp = tid >> 5, lane = tid & 31;
    const int gq = lane >> 2, tq = lane & 3;
    const int sel = lane >> 3, l7 = lane & 7;
    const int wm = warp << 4;

    const unsigned offA = (((sel&1)*8 + l7)*SROW + (sel>>1)*8)*2;
    const unsigned offB = (((sel>>1)*8 + l7)*SROW + (sel&1)*8)*2;
    const int sr = tid >> 1, cb = (tid & 1) * 32;
    unsigned asA[2], bsB[2], adst[2], bdst[2];
    #pragma unroll
    for (int s=0;s<2;s++){
        asA[s]  = smem_u32(Asb[s]) + wm*SROWB + offA;
        bsB[s]  = smem_u32(Bsb[s]) + offB;
        adst[s] = smem_u32(Asb[s]) + (sr*SROW + cb)*2;
        bdst[s] = smem_u32(Bsb[s]) + (sr*SROW + cb)*2;
    }

    const __half* arow;
    {
        int grow = m0 + sr;
        if (mode==0)      arow = g_xh + (size_t)grow*DMODEL;
        else if (mode==1) arow = (grow < MEMLEN*BATCH) ? g_memh + (size_t)grow*DMODEL
                                                       : g_xh + (size_t)(grow - MEMLEN*BATCH)*DMODEL;
        else              arow = g_posh + (size_t)grow*DMODEL;
    }
    const __half* brow = Wt + (size_t)(n0 + sr)*DMODEL;

    // prologue: issue chunk 0 into buffer 0
    #pragma unroll
    for (int q=0;q<4;q++){
        asm volatile("cp.async.cg.shared.global [%0], [%1], 16;"
            :: "r"(adst[0] + q*16), "l"(arow + cb + q*8));
        asm volatile("cp.async.cg.shared.global [%0], [%1], 16;"
            :: "r"(bdst[0] + q*16), "l"(brow + cb + q*8));
    }
    asm volatile("cp.async.commit_group;");
    asm volatile("cp.async.wait_group 0;");
    __syncthreads();

    float acc[16][4];
    #pragma unroll
    for (int ni=0;ni<16;ni++)
        #pragma unroll
        for (int c=0;c<4;c++) acc[ni][c]=0.f;

    for (int c=0;c<16;c++){
        const int s = c & 1;
        if (c < 15){
            const __half* asrc = arow + (c+1)*64 + cb;
            const __half* bsrc = brow + (c+1)*64 + cb;
            #pragma unroll
            for (int q=0;q<4;q++){
                asm volatile("cp.async.cg.shared.global [%0], [%1], 16;"
                    :: "r"(adst[s^1] + q*16), "l"(asrc + q*8));
                asm volatile("cp.async.cg.shared.global [%0], [%1], 16;"
                    :: "r"(bdst[s^1] + q*16), "l"(bsrc + q*8));
            }
            asm volatile("cp.async.commit_group;");
        }
        #pragma unroll
        for (int kk=0;kk<64;kk+=16){
            unsigned a0,a1,a2,a3;
            ldsm4(a0,a1,a2,a3, asA[s] + kk*2);
            #pragma unroll
            for (int q=0;q<8;q++){
                unsigned b0,b1,b2,b3;
                ldsm4(b0,b1,b2,b3, bsB[s] + q*2304 + kk*2);
                mma_f16(acc[2*q  ], a0,a1,a2,a3, b0,b1);
                mma_f16(acc[2*q+1], a0,a1,a2,a3, b2,b3);
            }
        }
        if (c < 15)
            asm volatile("cp.async.wait_group 0;");
        __syncthreads();
    }

    const int row0 = m0 + wm + gq, row1 = row0 + 8;
    #pragma unroll
    for (int ni=0;ni<16;ni++){
        const int col = n0 + ni*8 + 2*tq;
        qkvr_store(mode, row0, col, pack_h2(acc[ni][0], acc[ni][1]));
        qkvr_store(mode, row1, col, pack_h2(acc[ni][2], acc[ni][3]));
    }
}

// ---------------- BD strip: BDslot[128][132] = Q . Rs^T + vR (folded) ------------
__device__ __forceinline__ void compute_strip(unsigned qs_u32, unsigned rs_u32,
                                              float* BDslot, const float* vRslot,
                                              int warp, int lane)
{
    const int sel = lane >> 3, l7 = lane & 7;
    const int gq = lane >> 2, tq = lane & 3;
    const int wmb = (warp >> 1) * 32, wnb = (warp & 1) * 64;
    const unsigned offA = (((sel&1)*8 + l7)*SROW + (sel>>1)*8)*2;
    const unsigned offB = (((sel>>1)*8 + l7)*SROW + (sel&1)*8)*2;

    float abd[2][2][4][4];
    #pragma unroll
    for (int pass=0; pass<2; pass++){
        #pragma unroll
        for (int mi=0;mi<2;mi++)
            #pragma unroll
            for (int ni=0;ni<4;ni++)
                #pragma unroll
                for (int e=0;e<4;e++) abd[pass][mi][ni][e]=0.f;
        #pragma unroll
        for (int kk=0;kk<64;kk+=16){
            unsigned am[2][4];
            #pragma unroll
            for (int mi=0;mi<2;mi++)
                ldsm4(am[mi][0],am[mi][1],am[mi][2],am[mi][3],
                      qs_u32 + (wmb + mi*16)*SROWB + offA + kk*2);
            #pragma unroll
            for (int q=0;q<2;q++){
                unsigned b0,b1,b2,b3;
                ldsm4(b0,b1,b2,b3,
                      rs_u32 + (wnb + pass*32 + 16*q)*SROWB + offB + kk*2);
                mma_f16(abd[pass][0][2*q  ], am[0][0],am[0][1],am[0][2],am[0][3], b0,b1);
                mma_f16(abd[pass][0][2*q+1], am[0][0],am[0][1],am[0][2],am[0][3], b2,b3);
                mma_f16(abd[pass][1][2*q  ], am[1][0],am[1][1],am[1][2],am[1][3], b0,b1);
                mma_f16(abd[pass][1][2*q+1], am[1][0],am[1][1],am[1][2],am[1][3], b2,b3);
            }
        }
    }
    __syncthreads();   // vRslot writes (pre-call, program order) visible to all
    #pragma unroll
    for (int pass=0; pass<2; pass++)
        #pragma unroll
        for (int mi=0;mi<2;mi++)
            #pragma unroll
            for (int rr=0;rr<2;rr++){
                const int il = wmb + mi*16 + gq + rr*8;
                #pragma unroll
                for (int ni=0;ni<4;ni++){
                    const int pl = wnb + pass*32 + ni*8 + 2*tq;
                    float2 v = { abd[pass][mi][ni][rr*2+0] + vRslot[pl],
                                 abd[pass][mi][ni][rr*2+1] + vRslot[pl+1] };
                    *(float2*)&BDslot[il*BDS + pl] = v;
                }
            }
}

// ---------------- flash: scores (AC + strip-shared BD) + exp + PV ----------------
#define FL_SMEM_BYTES 210944
__global__ __launch_bounds__(256) void flash_mma(const float* __restrict__ ubias,
                                                 const float* __restrict__ vbias)
{
    const int gg = blockIdx.y, h = gg & (NH-1);
    const int bi = 7 - blockIdx.x;            // heavy CTAs first
    const int i0 = bi << 7;

    extern __shared__ char smr[];
    __half* Qs = (__half*)smr;                 // [128][72]
    __half* Ks = (__half*)(smr + 18432);       // [128][72]
    __half* Rs = (__half*)(smr + 36864);       // [128][72]
    __half* Vs = (__half*)(smr + 55296);       // [128 t][72 d]
    float*  BD0 = (float*)(smr + 73728);       // [128][132]
    float*  BD1 = (float*)(smr + 141312);
    float*  uKs = (float*)(smr + 208896);      // [128]
    float*  vR0 = (float*)(smr + 209408);      // [128]
    float*  vR1 = (float*)(smr + 209920);
    float*  u_s = (float*)(smr + 210432);      // [64]
    float*  v_s = (float*)(smr + 210688);

    const int tid = threadIdx.x;
    const int warp = tid >> 5, lane = tid & 31;
    const int gq = lane >> 2, tq = lane & 3;
    const int sel = lane >> 3, l7 = lane & 7;
    const int wm = warp << 4;                  // 16 AC rows per warp

    const unsigned qs_u32 = smem_u32(Qs);
    const unsigned ks_u32 = smem_u32(Ks);
    const unsigned rs_u32 = smem_u32(Rs);
    const unsigned vs_u32 = smem_u32(Vs);
    const unsigned offA = (((sel&1)*8 + l7)*SROW + (sel>>1)*8)*2;
    const unsigned offB = (((sel>>1)*8 + l7)*SROW + (sel&1)*8)*2;
    const unsigned qsA = qs_u32 + wm*SROWB + offA;
    const unsigned ksB = ks_u32 + offB;
    const unsigned vsB = vs_u32 + offA;

    const int sr = tid >> 1, cb = (tid & 1) * 32;

    // ---- prologue: stage Q, biases, strip 0 ----
    {
        const __half* qrow = g_q + (((size_t)gg*LQ + i0 + sr) << 6) + cb;
        #pragma unroll
        for (int q=0;q<4;q++)
            *(uint4*)&Qs[sr*SROW + cb + q*8] = *(const uint4*)(qrow + q*8);
        if (tid < 64)       u_s[tid]    = ubias[(h<<6) + tid];
        else if (tid < 128) v_s[tid-64] = vbias[(h<<6) + tid - 64];
        const int ps0 = (7 - bi) << 7;
        const __half* rrow = g_r + (((size_t)gg*TT + ps0 + sr) << 6) + cb;
        #pragma unroll
        for (int q=0;q<4;q++)
            *(uint4*)&Rs[sr*SROW + cb + q*8] = *(const uint4*)(rrow + q*8);
    }
    __syncthreads();
    if (tid >= 128){
        const int c = tid - 128;
        float s = 0.f;
        #pragma unroll
        for (int d=0;d<64;d++) s += v_s[d] * __half2float(Rs[c*SROW + d]);
        vR0[c] = s;
    }
    compute_strip(qs_u32, rs_u32, BD0, vR0, warp, lane);

    float acc_pv[8][4];
    #pragma unroll
    for (int ni=0;ni<8;ni++)
        #pragma unroll
        for (int c=0;c<4;c++) acc_pv[ni][c]=0.f;
    float rs_0 = 0.f, rs_1 = 0.f;

    const int jt_max = bi + 8;
    for (int jt=0; jt<=jt_max; jt++){
        const int j0 = jt << 7;
        const bool doStrip = (jt < jt_max);
        __syncthreads();                       // S1
        // stage K, V (and R for strip jt+1)
        {
            const __half* krow = g_k + (((size_t)gg*TT + j0 + sr) << 6) + cb;
            const __half* vrow = g_v + (((size_t)gg*TT + j0 + sr) << 6) + cb;
            #pragma unroll
            for (int q=0;q<4;q++){
                *(uint4*)&Ks[sr*SROW + cb + q*8] = *(const uint4*)(krow + q*8);
                *(uint4*)&Vs[sr*SROW + cb + q*8] = *(const uint4*)(vrow + q*8);
            }
            if (doStrip){
                const int ps = (jt + 1 - bi + 7) << 7;
                const __half* rrow = g_r + (((size_t)gg*TT + ps + sr) << 6) + cb;
                #pragma unroll
                for (int q=0;q<4;q++)
                    *(uint4*)&Rs[sr*SROW + cb + q*8] = *(const uint4*)(rrow + q*8);
            }
        }
        __syncthreads();                       // S2
        if (tid < 128){
            float s = 0.f;
            #pragma unroll
            for (int d=0;d<64;d++) s += u_s[d] * __half2float(Ks[tid*SROW + d]);
            uKs[tid] = s;
        } else if (doStrip){
            const int c = tid - 128;
            float s = 0.f;
            #pragma unroll
            for (int d=0;d<64;d++) s += v_s[d] * __half2float(Rs[c*SROW + d]);
            (((jt+1)&1) ? vR1 : vR0)[c] = s;
        }
        // AC = Q.K^T (warp tile 16x128) via ldmatrix
        float acc[16][4];
        #pragma unroll
        for (int ni=0;ni<16;ni++)
            #pragma unroll
            for (int c=0;c<4;c++) acc[ni][c]=0.f;
        #pragma unroll
        for (int kk=0;kk<64;kk+=16){
            unsigned a0,a1,a2,a3;
            ldsm4(a0,a1,a2,a3, qsA + kk*2);
            #pragma unroll
            for (int q=0;q<8;q++){
                unsigned b0,b1,b2,b3;
                ldsm4(b0,b1,b2,b3, ksB + q*2304 + kk*2);
                mma_f16(acc[2*q  ], a0,a1,a2,a3, b0,b1);
                mma_f16(acc[2*q+1], a0,a1,a2,a3, b2,b3);
            }
        }
        if (doStrip)
            compute_strip(qs_u32, rs_u32, ((jt+1)&1) ? BD1 : BD0,
                          ((jt+1)&1) ? vR1 : vR0, warp, lane);
        __syncthreads();                       // S3
        // gather + exp + mask + write p + row sums
        const bool isDiag = (jt == jt_max);
        const float* BDa = (jt & 1) ? BD1 : BD0;
        const float* BDb = (jt & 1) ? BD0 : BD1;
        const int il0 = wm + gq, il1 = il0 + 8;
        unsigned pfrag[16][2];
        __half* prow0 = g_p + ((size_t)gg*LQ + i0 + il0)*TT + j0;
        __half* prow1 = g_p + ((size_t)gg*LQ + i0 + il1)*TT + j0;
        #pragma unroll
        for (int ni=0;ni<16;ni++){
            const int jl = ni*8 + 2*tq;
            const int o00 = jl - il0 + 127;
            const int o10 = jl - il1 + 127;
            float bd00 = (o00   < 128) ? BDa[il0*BDS + o00    ] : BDb[il0*BDS + o00-128];
            float bd01 = (o00+1 < 128) ? BDa[il0*BDS + o00 + 1] : BDb[il0*BDS + o00-127];
            float bd10 = (o10   < 128) ? BDa[il1*BDS + o10    ] : BDb[il1*BDS + o10-128];
            float bd11 = (o10+1 < 128) ? BDa[il1*BDS + o10 + 1] : BDb[il1*BDS + o10-127];
            const float u0 = uKs[jl], u1 = uKs[jl+1];
            float p0 = __expf((acc[ni][0] + bd00 + u0)*SCALE_F - EXPC);
            float p1 = __expf((acc[ni][1] + bd01 + u1)*SCALE_F - EXPC);
            float p2 = __expf((acc[ni][2] + bd10 + u0)*SCALE_F - EXPC);
            float p3 = __expf((acc[ni][3] + bd11 + u1)*SCALE_F - EXPC);
            if (isDiag){
                if (jl   > il0) p0 = 0.f;
                if (jl+1 > il0) p1 = 0.f;
                if (jl   > il1) p2 = 0.f;
                if (jl+1 > il1) p3 = 0.f;
            }
            rs_0 += p0 + p1;
            rs_1 += p2 + p3;
            unsigned lo = pack_h2(p0, p1), hi = pack_h2(p2, p3);
            *reinterpret_cast<unsigned*>(prow0 + jl) = lo;
            *reinterpret_cast<unsigned*>(prow1 + jl) = hi;
            pfrag[ni][0] = lo;
            pfrag[ni][1] = hi;
        }
        // PV: acc_pv += P(tile) @ V(tile), V frags via ldmatrix.trans
        #pragma unroll
        for (int s=0;s<8;s++){
            unsigned a0 = pfrag[2*s][0], a1 = pfrag[2*s][1];
            unsigned a2 = pfrag[2*s+1][0], a3 = pfrag[2*s+1][1];
            #pragma unroll
            for (int q=0;q<4;q++){
                unsigned b0,b1,b2,b3;
                ldsm4t(b0,b1,b2,b3, vsB + s*2304 + q*32);
                mma_f16(acc_pv[2*q  ], a0,a1,a2,a3, b0,b1);
                mma_f16(acc_pv[2*q+1], a0,a1,a2,a3, b2,b3);
            }
        }
    }

    // epilogue: row sums, normalize, write av
    rs_0 += __shfl_xor_sync(0xffffffffu, rs_0, 1);
    rs_0 += __shfl_xor_sync(0xffffffffu, rs_0, 2);
    rs_1 += __shfl_xor_sync(0xffffffffu, rs_1, 1);
    rs_1 += __shfl_xor_sync(0xffffffffu, rs_1, 2);
    const int row0 = i0 + wm + gq, row1 = row0 + 8;
    if (tq == 0){
        g_rs[gg*LQ + row0] = rs_0;
        g_rs[gg*LQ + row1] = rs_1;
    }
    const float inv0 = 1.f / rs_0, inv1 = 1.f / rs_1;
    const int b = gg >> 4;
    __half* dst0 = g_av + (size_t)(row0*BATCH + b)*DMODEL + (h<<6);
    __half* dst1 = g_av + (size_t)(row1*BATCH + b)*DMODEL + (h<<6);
    #pragma unroll
    for (int ni=0;ni<8;ni++){
        const int d = ni*8 + 2*tq;
        *reinterpret_cast<unsigned*>(dst0 + d) = pack_h2(acc_pv[ni][0]*inv0, acc_pv[ni][1]*inv0);
        *reinterpret_cast<unsigned*>(dst1 + d) = pack_h2(acc_pv[ni][2]*inv1, acc_pv[ni][3]*inv1);
    }
}

// ---------------- attn_matrix = mean over (b,h) of p/rs --------------------------
__global__ __launch_bounds__(256) void attnmat_kernel(float* __restrict__ out)
{
    const int i  = blockIdx.y;
    const int j0 = blockIdx.x << 9;            // 4 tiles of 512
    const int jmax = i + MEMLEN;
    const int tid = threadIdx.x;
    const int jq = tid & 63;
    const int gsel = tid >> 6;
    const int j = j0 + jq*8;
    __shared__ float red[256][9];

    float a[8] = {0.f,0.f,0.f,0.f,0.f,0.f,0.f,0.f};
    if (j0 <= jmax){
        #pragma unroll
        for (int gi=0; gi<8; gi++){
            int g = gsel*8 + gi;
            float inv = 1.f / g_rs[g*LQ + i];
            uint4 raw = *(const uint4*)(g_p + ((size_t)g*LQ + i)*TT + j);
            const __half2* hp = (const __half2*)&raw;
            #pragma unroll
            for (int e=0;e<4;e++){
                float2 f = __half22float2(hp[e]);
                a[2*e]   += f.x * inv;
                a[2*e+1] += f.y * inv;
            }
        }
        #pragma unroll
        for (int e=0;e<8;e++) if (j+e > jmax) a[e] = 0.f;
    }
    #pragma unroll
    for (int e=0;e<8;e++) red[tid][e] = a[e];
    __syncthreads();
    if (tid < 64){
        const float k = 1.f/NG;
        float o[8];
        #pragma unroll
        for (int e=0;e<8;e++)
            o[e] = (red[tid][e] + red[tid+64][e] + red[tid+128][e] + red[tid+192][e]) * k;
        float* dst = out + (size_t)i*TT + j0 + tid*8;
        *(float4*)dst     = make_float4(o[0],o[1],o[2],o[3]);
        *(float4*)(dst+4) = make_float4(o[4],o[5],o[6],o[7]);
    }
}

// ---------------- Wo GEMM + residual (fp16 MMA): g_h = x + g_av @ Wo ------------
__global__ __launch_bounds__(256) void wo_mma(const float* __restrict__ x)
{
    const int m0 = blockIdx.y << 7;
    const int n0 = blockIdx.x << 6;

    __shared__ __half   As[128*40];
    __shared__ unsigned Bs[16*72];

    const int tid = threadIdx.x;
    const int warp = tid >> 5, lane = tid & 31;
    const int gq = lane >> 2, tq = lane & 3;
    const int wm = (warp >> 1) * 32, wn = (warp & 1) * 32;
    const unsigned* As2 = (const unsigned*)As;

    float acc[2][4][4];
    #pragma unroll
    for (int mi=0;mi<2;mi++)
        #pragma unroll
        for (int ni=0;ni<4;ni++)
            #pragma unroll
            for (int c=0;c<4;c++) acc[mi][ni][c]=0.f;

    const int a_r = tid >> 1;
    const int a_cb = (tid & 1) * 16;
    const __half* arow = g_av + (size_t)(m0 + a_r)*DMODEL + a_cb;
    const int b_k2 = tid >> 4;
    const int b_cb = (tid & 15) * 4;

    for (int k0=0;k0<DMODEL;k0+=32){
        {
            __half* Ad = As + a_r*40 + a_cb;
            *(uint4*)Ad     = *(const uint4*)(arow + k0);
            *(uint4*)(Ad+8) = *(const uint4*)(arow + k0 + 8);
            const unsigned* bsrc = g_woi + (size_t)((k0>>1) + b_k2)*DMODEL + n0 + b_cb;
            *(uint4*)&Bs[b_k2*72 + b_cb] = *(const uint4*)bsrc;
        }
        __syncthreads();
        #pragma unroll
        for (int kk=0;kk<32;kk+=16){
            const int k2 = kk >> 1;
            unsigned a[2][4], bfr[4][2];
            #pragma unroll
            for (int mi=0;mi<2;mi++){
                int m = wm + mi*16;
                a[mi][0] = As2[(m+gq  )*20 + k2 + tq  ];
                a[mi][1] = As2[(m+gq+8)*20 + k2 + tq  ];
                a[mi][2] = As2[(m+gq  )*20 + k2 + tq+4];
                a[mi][3] = As2[(m+gq+8)*20 + k2 + tq+4];
            }
            #pragma unroll
            for (int ni=0;ni<4;ni++){
                int n = wn + ni*8 + gq;
                bfr[ni][0] = Bs[(k2+tq  )*72 + n];
                bfr[ni][1] = Bs[(k2+tq+4)*72 + n];
            }
            #pragma unroll
            for (int mi=0;mi<2;mi++)
                #pragma unroll
                for (int ni=0;ni<4;ni++)
                    mma_f16(acc[mi][ni], a[mi][0],a[mi][1],a[mi][2],a[mi][3], bfr[ni][0],bfr[ni][1]);
        }
        __syncthreads();
    }

    #pragma unroll
    for (int mi=0;mi<2;mi++)
        #pragma unroll
        for (int rr=0;rr<2;rr++){
            const int row = m0 + wm + mi*16 + gq + rr*8;
            #pragma unroll
            for (int ni=0;ni<4;ni++){
                const int col = n0 + wn + ni*8 + 2*tq;
                float2 xv = *(const float2*)&x[(size_t)row*DMODEL + col];
                float2 val = { acc[mi][ni][rr*2+0] + xv.x,
                               acc[mi][ni][rr*2+1] + xv.y };
                *(float2*)&g_h[(size_t)row*DMODEL + col] = val;
            }
        }
}

// ---------------- layernorm ------------------------------------------------------
__global__ __launch_bounds__(256) void ln_kernel(const float* __restrict__ gamma,
                                                 const float* __restrict__ beta,
                                                 float* __restrict__ out)
{
    const int row = blockIdx.x;
    const float* hr = g_h + (size_t)row*DMODEL;
    const int c = threadIdx.x * 4;
    float4 v = *(const float4*)(hr + c);
    float s = v.x+v.y+v.z+v.w;
    s = blockSum(s);
    const float mu = s * (1.f/DMODEL);
    float dx = v.x-mu, dy = v.y-mu, dz = v.z-mu, dw = v.w-mu;
    float sq = dx*dx+dy*dy+dz*dz+dw*dw;
    sq = blockSum(sq);
    const float inv = rsqrtf(sq*(1.f/DMODEL) + 1e-5f);
    float4 gm = *(const float4*)(gamma + c);
    float4 bt = *(const float4*)(beta + c);
    float4 o;
    o.x = dx*inv*gm.x + bt.x;
    o.y = dy*inv*gm.y + bt.y;
    o.z = dz*inv*gm.z + bt.z;
    o.w = dw*inv*gm.w + bt.w;
    *(float4*)(out + (size_t)row*DMODEL + c) = o;
}

// ---------------- launch ----------------------------------------------------------
extern "C" void kernel_launch(void* const* d_in, const int* in_sizes, int n_in,
                              void* d_out, int out_size)
{
    const float* x        = (const float*)d_in[0];
    const float* pos_emb  = (const float*)d_in[1];
    const float* memory   = (const float*)d_in[2];
    const float* ubias    = (const float*)d_in[3];
    const float* vbias    = (const float*)d_in[4];
    const float* Wq       = (const float*)d_in[6];
    const float* Wkv      = (const float*)d_in[7];
    const float* Wrel     = (const float*)d_in[8];
    const float* Wo       = (const float*)d_in[9];
    const float* gamma    = (const float*)d_in[10];
    const float* beta     = (const float*)d_in[11];
    float* out    = (float*)d_out;
    float* out_am = out + (size_t)LQ*BATCH*DMODEL;

    cudaFuncSetAttribute(flash_mma, cudaFuncAttributeMaxDynamicSharedMemorySize, FL_SMEM_BYTES);
    cudaFuncSetAttribute(qkvr_mma,  cudaFuncAttributeMaxDynamicSharedMemorySize, QK_SMEM_BYTES);

    cvt_all<<<5632, 256>>>(x, memory, pos_emb, Wq, Wkv, Wrel, Wo);
    qkvr_mma<<<896, 256, QK_SMEM_BYTES>>>();
    flash_mma<<<dim3(8, NG), 256, FL_SMEM_BYTES>>>(ubias, vbias);
    attnmat_kernel<<<dim3(4, LQ), 256>>>(out_am);
    wo_mma<<<dim3(16,16), 256>>>(x);
    ln_kernel<<<LQ*BATCH, 256>>>(gamma, beta, out);
}

// round 15
// speedup vs baseline: 1.2469x; 1.0669x over previous
#include <cuda_runtime.h>
#include <cuda_fp16.h>
#include <math.h>
#include <stdint.h>

#define LQ      1024
#define BATCH   2
#define DMODEL  1024
#define NH      16
#define DHD     64
#define MEMLEN  1024
#define TT      2048
#define NG      (BATCH*NH)
#define SCALE_F 0.125f
#define EXPC    8.0f
#define SROW    72          // halves per staged row
#define SROWB   144         // bytes per staged row
#define BDSH    136         // halves per fp16 BD strip row

// ---------------- scratch -------------------------------------------------------
__device__ __half g_q [NG*LQ*DHD];
__device__ __half g_k [NG*TT*DHD];
__device__ __half g_v [NG*TT*DHD];
__device__ __half g_r [NG*TT*DHD];
__device__ __half g_p [(size_t)NG*LQ*TT];            // unnormalized e^(s-8) (fp16)
__device__ float  g_rs[NG*LQ];                       // row sums of e^(s-8)
__device__ float  g_uk[NG*TT];                       // u . k_t
__device__ float  g_vr[NG*TT];                       // v . r_t
__device__ __half g_av[LQ*BATCH*NH*DHD];
__device__ float  g_h [LQ*BATCH*DMODEL];
// fp16 pre-converted inputs / weights
__device__ __half   g_xh   [LQ*BATCH*DMODEL];
__device__ __half   g_memh [MEMLEN*BATCH*DMODEL];
__device__ __half   g_posh [TT*BATCH*DMODEL];
__device__ __half   g_wqt  [1024*1024];              // W^T [n][k] fp16
__device__ __half   g_wkvt [2048*1024];
__device__ __half   g_wrelt[1024*1024];
__device__ unsigned g_woi  [512*1024];               // (W[2k],W[2k+1]) half2 pairs (wo)

// ---------------- helpers ---------------------------------------------------------
__device__ __forceinline__ unsigned pack_h2(float a, float b){
    __half2 h = __floats2half2_rn(a, b);
    return *reinterpret_cast<unsigned*>(&h);
}
__device__ __forceinline__ void mma_f16(float c[4],
                                        unsigned a0, unsigned a1, unsigned a2, unsigned a3,
                                        unsigned b0, unsigned b1){
    asm volatile("mma.sync.aligned.m16n8k16.row.col.f32.f16.f16.f32 "
        "{%0,%1,%2,%3}, {%4,%5,%6,%7}, {%8,%9}, {%0,%1,%2,%3};"
        : "+f"(c[0]), "+f"(c[1]), "+f"(c[2]), "+f"(c[3])
        : "r"(a0), "r"(a1), "r"(a2), "r"(a3), "r"(b0), "r"(b1));
}
__device__ __forceinline__ unsigned smem_u32(const void* p){
    return (unsigned)__cvta_generic_to_shared(p);
}
__device__ __forceinline__ void ldsm4(unsigned &r0, unsigned &r1, unsigned &r2, unsigned &r3, unsigned a){
    asm volatile("ldmatrix.sync.aligned.m8n8.x4.shared.b16 {%0,%1,%2,%3}, [%4];"
        : "=r"(r0),"=r"(r1),"=r"(r2),"=r"(r3) : "r"(a));
}
__device__ __forceinline__ void ldsm4t(unsigned &r0, unsigned &r1, unsigned &r2, unsigned &r3, unsigned a){
    asm volatile("ldmatrix.sync.aligned.m8n8.x4.trans.shared.b16 {%0,%1,%2,%3}, [%4];"
        : "=r"(r0),"=r"(r1),"=r"(r2),"=r"(r3) : "r"(a));
}
__device__ __forceinline__ void cpasync16(unsigned dst, const void* src){
    asm volatile("cp.async.cg.shared.global [%0], [%1], 16;" :: "r"(dst), "l"(src));
}

__device__ __forceinline__ float blockSum(float v){
    __shared__ float sm[32];
    int lane = threadIdx.x & 31, w = threadIdx.x >> 5;
    #pragma unroll
    for (int o=16;o>0;o>>=1) v += __shfl_xor_sync(0xffffffffu, v, o);
    if (lane==0) sm[w] = v;
    __syncthreads();
    float r = (threadIdx.x < 8) ? sm[threadIdx.x] : 0.f;
    if (w==0){
        #pragma unroll
        for (int o=4;o>0;o>>=1) r += __shfl_xor_sync(0xffffffffu, r, o);
        if (lane==0) sm[0]=r;
    }
    __syncthreads();
    r = sm[0];
    __syncthreads();
    return r;
}

// ---------------- fp16 pre-conversion -------------------------------------------
__device__ __forceinline__ void cvt_plain(const float* __restrict__ s, __half* d, int b, int t){
    const int idx = b*2048 + t*8;
    float4 v0 = *(const float4*)(s+idx), v1 = *(const float4*)(s+idx+4);
    unsigned u[4] = { pack_h2(v0.x,v0.y), pack_h2(v0.z,v0.w),
                      pack_h2(v1.x,v1.y), pack_h2(v1.z,v1.w) };
    *(uint4*)&d[idx] = *(uint4*)u;
}
__device__ __forceinline__ void cvt_inter(const float* __restrict__ W, unsigned* d,
                                          int b, int t, int lgN){
    const int p = b*1024 + t*4;
    const int N = 1 << lgN;
    const int k2 = p >> lgN, n = p & (N-1);
    const float* r0 = W + ((size_t)k2*2)*N + n;
    float4 a = *(const float4*)r0;
    float4 c = *(const float4*)(r0 + N);
    unsigned u[4] = { pack_h2(a.x,c.x), pack_h2(a.y,c.y),
                      pack_h2(a.z,c.z), pack_h2(a.w,c.w) };
    *(uint4*)&d[p] = *(uint4*)u;
}
__device__ void cvt_wt_tile(const float* __restrict__ W, __half* Wt, int N,
                            int ky, int nx, int tid){
    __shared__ float buf[64][65];
    const int k0 = ky*64, n0c = nx*64;
    const int kr = tid>>2, nc = (tid&3)*16;
    #pragma unroll
    for (int q=0;q<4;q++){
        float4 w = *(const float4*)(W + (size_t)(k0+kr)*N + n0c + nc + q*4);
        buf[kr][nc+q*4+0]=w.x; buf[kr][nc+q*4+1]=w.y;
        buf[kr][nc+q*4+2]=w.z; buf[kr][nc+q*4+3]=w.w;
    }
    __syncthreads();
    const int nr = tid>>2, kc = (tid&3)*16;
    unsigned u[8];
    #pragma unroll
    for (int e=0;e<8;e++)
        u[e] = pack_h2(buf[kc+2*e][nr], buf[kc+2*e+1][nr]);
    __half* dst = Wt + (size_t)(n0c+nr)*1024 + k0 + kc;
    *(uint4*)dst     = *(uint4*)&u[0];
    *(uint4*)(dst+8) = *(uint4*)&u[4];
}
__global__ __launch_bounds__(256) void cvt_all(const float* __restrict__ x,
                                               const float* __restrict__ memory,
                                               const float* __restrict__ pos_emb,
                                               const float* __restrict__ Wq,
                                               const float* __restrict__ Wkv,
                                               const float* __restrict__ Wrel,
                                               const float* __restrict__ Wo)
{
    const int bid = blockIdx.x, tid = threadIdx.x;
    if      (bid < 1024) cvt_plain(x,       g_xh,   bid,        tid);
    else if (bid < 2048) cvt_plain(memory,  g_memh, bid-1024,   tid);
    else if (bid < 4096) cvt_plain(pos_emb, g_posh, bid-2048,   tid);
    else if (bid < 4608) cvt_inter(Wo, g_woi, bid-4096, tid, 10);
    else {
        int t = bid - 4608;
        if (t < 256)      cvt_wt_tile(Wq,   g_wqt,   1024, t>>4,        t&15,        tid);
        else if (t < 768) cvt_wt_tile(Wkv,  g_wkvt,  2048, (t-256)>>5,  (t-256)&31,  tid);
        else              cvt_wt_tile(Wrel, g_wrelt, 1024, (t-768)>>4,  (t-768)&15,  tid);
    }
}

// ---------------- uk/vr precompute: g_uk = u.k_t, g_vr = v.r_t -------------------
__global__ __launch_bounds__(256) void ukvr_kernel(const float* __restrict__ ubias,
                                                   const float* __restrict__ vbias)
{
    const int g = blockIdx.y, h = g & (NH-1);
    const int tid = threadIdx.x;
    const int which = tid >> 7;
    const int sub = tid & 127;
    const int t = blockIdx.x*32 + (sub >> 2);
    const int rq = sub & 3;
    const __half* src = (which ? g_r : g_k) + (((size_t)g*TT + t) << 6) + rq*16;
    const float* bs = (which ? vbias : ubias) + (h << 6) + rq*16;
    uint4 u0 = *(const uint4*)src, u1 = *(const uint4*)(src + 8);
    const __half* h0 = (const __half*)&u0;
    const __half* h1 = (const __half*)&u1;
    float s = 0.f;
    #pragma unroll
    for (int e=0;e<8;e++) s += __half2float(h0[e]) * bs[e];
    #pragma unroll
    for (int e=0;e<8;e++) s += __half2float(h1[e]) * bs[8+e];
    s += __shfl_xor_sync(0xffffffffu, s, 1);
    s += __shfl_xor_sync(0xffffffffu, s, 2);
    if (rq == 0) (which ? g_vr : g_uk)[g*TT + t] = s;
}

// ---------------- QKVR projection GEMM (fp16 MMA, cp.async double-buffered) ------
#define QK_SMEM_BYTES (4*128*SROW*2)

__device__ __forceinline__ void qkvr_store(int mode, int row, int col, unsigned hv){
    const int t = row >> 1, bb = row & 1;
    if (mode==0){
        int h = col >> 6, d = col & 63;
        *reinterpret_cast<unsigned*>(&g_q[(((size_t)(bb*NH+h)*LQ + t)<<6) + d]) = hv;
    } else if (mode==1){
        int c2 = col; __half* dst = g_k;
        if (c2 >= NH*DHD){ dst = g_v; c2 -= NH*DHD; }
        int h = c2 >> 6, d = c2 & 63;
        *reinterpret_cast<unsigned*>(&dst[(((size_t)(bb*NH+h)*TT + t)<<6) + d]) = hv;
    } else {
        int h = col >> 6, d = col & 63;
        *reinterpret_cast<unsigned*>(&g_r[(((size_t)(bb*NH+h)*TT + t)<<6) + d]) = hv;
    }
}

__global__ __launch_bounds__(256) void qkvr_mma()
{
    extern __shared__ __half smqk[];
    __half* Asb[2] = { smqk,              smqk +   128*SROW };
    __half* Bsb[2] = { smqk + 2*128*SROW, smqk + 3*128*SROW };

    int bid = blockIdx.x;
    int mode, m0, n0;
    const __half* Wt;
    if (bid < 128)      { mode=0; m0=(bid>>3)<<7;  n0=(bid&7)<<7;  Wt=g_wqt;  }
    else if (bid < 640) { int t=bid-128; mode=1; m0=(t>>4)<<7; n0=(t&15)<<7; Wt=g_wkvt; }
    else                { int t=bid-640; mode=2; m0=(t>>3)<<7; n0=(t&7)<<7;  Wt=g_wrelt;}

    const int tid = threadIdx.x;
    const int warp = tid >> 5, lane = tid & 31;
    const int gq = lane >> 2, tq = lane & 3;
    const int sel = lane >> 3, l7 = lane & 7;
    const int wm = warp << 4;

    const unsigned offA = (((sel&1)*8 + l7)*SROW + (sel>>1)*8)*2;
    const unsigned offB = (((sel>>1)*8 + l7)*SROW + (sel&1)*8)*2;
    const int sr = tid >> 1, cb = (tid & 1) * 32;
    unsigned asA[2], bsB[2], adst[2], bdst[2];
    #pragma unroll
    for (int s=0;s<2;s++){
        asA[s]  = smem_u32(Asb[s]) + wm*SROWB + offA;
        bsB[s]  = smem_u32(Bsb[s]) + offB;
        adst[s] = smem_u32(Asb[s]) + (sr*SROW + cb)*2;
        bdst[s] = smem_u32(Bsb[s]) + (sr*SROW + cb)*2;
    }

    const __half* arow;
    {
        int grow = m0 + sr;
        if (mode==0)      arow = g_xh + (size_t)grow*DMODEL;
        else if (mode==1) arow = (grow < MEMLEN*BATCH) ? g_memh + (size_t)grow*DMODEL
                                                       : g_xh + (size_t)(grow - MEMLEN*BATCH)*DMODEL;
        else              arow = g_posh + (size_t)grow*DMODEL;
    }
    const __half* brow = Wt + (size_t)(n0 + sr)*DMODEL;

    #pragma unroll
    for (int q=0;q<4;q++){
        cpasync16(adst[0] + q*16, arow + cb + q*8);
        cpasync16(bdst[0] + q*16, brow + cb + q*8);
    }
    asm volatile("cp.async.commit_group;");
    asm volatile("cp.async.wait_group 0;");
    __syncthreads();

    float acc[16][4];
    #pragma unroll
    for (int ni=0;ni<16;ni++)
        #pragma unroll
        for (int c=0;c<4;c++) acc[ni][c]=0.f;

    for (int c=0;c<16;c++){
        const int s = c & 1;
        if (c < 15){
            const __half* asrc = arow + (c+1)*64 + cb;
            const __half* bsrc = brow + (c+1)*64 + cb;
            #pragma unroll
            for (int q=0;q<4;q++){
                cpasync16(adst[s^1] + q*16, asrc + q*8);
                cpasync16(bdst[s^1] + q*16, bsrc + q*8);
            }
            asm volatile("cp.async.commit_group;");
        }
        #pragma unroll
        for (int kk=0;kk<64;kk+=16){
            unsigned a0,a1,a2,a3;
            ldsm4(a0,a1,a2,a3, asA[s] + kk*2);
            #pragma unroll
            for (int q=0;q<8;q++){
                unsigned b0,b1,b2,b3;
                ldsm4(b0,b1,b2,b3, bsB[s] + q*2304 + kk*2);
                mma_f16(acc[2*q  ], a0,a1,a2,a3, b0,b1);
                mma_f16(acc[2*q+1], a0,a1,a2,a3, b2,b3);
            }
        }
        if (c < 15)
            asm volatile("cp.async.wait_group 0;");
        __syncthreads();
    }

    const int row0 = m0 + wm + gq, row1 = row0 + 8;
    #pragma unroll
    for (int ni=0;ni<16;ni++){
        const int col = n0 + ni*8 + 2*tq;
        qkvr_store(mode, row0, col, pack_h2(acc[ni][0], acc[ni][1]));
        qkvr_store(mode, row1, col, pack_h2(acc[ni][2], acc[ni][3]));
    }
}

// ---------------- flash SMEM layout ------------------------------------------------
// Qs 0..18432 | Ks[2] 18432.. | Rs[2] 55296.. | Vs[2] 92160.. | BDh[2] 129024.. | uKs[2] 198656..
#define KS_O(s)  (18432 + (s)*18432)
#define RS_O(s)  (55296 + (s)*18432)
#define VS_O(s)  (92160 + (s)*18432)
#define BD_O(s)  (129024 + (s)*34816)
#define UK_O(s)  (198656 + (s)*512)
#define FL_SMEM_BYTES 199680

__device__ __forceinline__ void flash_issue(char* smr, int s, int gg, int j0, int ps,
                                            int sr, int cb, int tid){
    const __half* krow = g_k + (((size_t)gg*TT + j0 + sr) << 6) + cb;
    const __half* vrow = g_v + (((size_t)gg*TT + j0 + sr) << 6) + cb;
    const int rg = min(ps + sr, TT-1);
    const __half* rrow = g_r + (((size_t)gg*TT + rg) << 6) + cb;
    const unsigned base = smem_u32(smr);
    const unsigned off = (sr*SROW + cb)*2;
    const unsigned kd = base + KS_O(s) + off;
    const unsigned rd = base + RS_O(s) + off;
    const unsigned vd = base + VS_O(s) + off;
    #pragma unroll
    for (int q=0;q<4;q++){
        cpasync16(kd + q*16, krow + q*8);
        cpasync16(vd + q*16, vrow + q*8);
        cpasync16(rd + q*16, rrow + q*8);
    }
    if (tid < 32)
        cpasync16(base + UK_O(s) + tid*16, g_uk + (size_t)gg*TT + j0 + tid*4);
}

// ---------------- BD strip (fp16 out, vr folded from global) ----------------------
__device__ __forceinline__ void compute_strip_f16(unsigned qs_u32, unsigned rs_base,
                                                  __half* BDslot, const float* vrrow,
                                                  int pstrip, int warp, int lane)
{
    const int sel = lane >> 3, l7 = lane & 7;
    const int gq = lane >> 2, tq = lane & 3;
    const int wmb = (warp >> 1) * 32, wnb = (warp & 1) * 64;
    const unsigned offA = (((sel&1)*8 + l7)*SROW + (sel>>1)*8)*2;
    const unsigned offB = (((sel>>1)*8 + l7)*SROW + (sel&1)*8)*2;
    const unsigned rs_u32 = rs_base + offB;

    float abd[2][2][4][4];
    #pragma unroll
    for (int pass=0; pass<2; pass++){
        #pragma unroll
        for (int mi=0;mi<2;mi++)
            #pragma unroll
            for (int ni=0;ni<4;ni++)
                #pragma unroll
                for (int e=0;e<4;e++) abd[pass][mi][ni][e]=0.f;
        #pragma unroll
        for (int kk=0;kk<64;kk+=16){
            unsigned am[2][4];
            #pragma unroll
            for (int mi=0;mi<2;mi++)
                ldsm4(am[mi][0],am[mi][1],am[mi][2],am[mi][3],
                      qs_u32 + (wmb + mi*16)*SROWB + offA + kk*2);
            #pragma unroll
            for (int q=0;q<2;q++){
                unsigned b0,b1,b2,b3;
                ldsm4(b0,b1,b2,b3,
                      rs_u32 + (wnb + pass*32 + 16*q)*SROWB + kk*2);
                mma_f16(abd[pass][0][2*q  ], am[0][0],am[0][1],am[0][2],am[0][3], b0,b1);
                mma_f16(abd[pass][0][2*q+1], am[0][0],am[0][1],am[0][2],am[0][3], b2,b3);
                mma_f16(abd[pass][1][2*q  ], am[1][0],am[1][1],am[1][2],am[1][3], b0,b1);
                mma_f16(abd[pass][1][2*q+1], am[1][0],am[1][1],am[1][2],am[1][3], b2,b3);
            }
        }
    }
    #pragma unroll
    for (int pass=0; pass<2; pass++)
        #pragma unroll
        for (int ni=0;ni<4;ni++){
            const int pl = wnb + pass*32 + ni*8 + 2*tq;
            const float vr0 = vrrow[min(pstrip + pl,     TT-1)];
            const float vr1 = vrrow[min(pstrip + pl + 1, TT-1)];
            #pragma unroll
            for (int mi=0;mi<2;mi++)
                #pragma unroll
                for (int rr=0;rr<2;rr++){
                    const int il = wmb + mi*16 + gq + rr*8;
                    *reinterpret_cast<unsigned*>(&BDslot[il*BDSH + pl]) =
                        pack_h2(abd[pass][mi][ni][rr*2+0] + vr0,
                                abd[pass][mi][ni][rr*2+1] + vr1);
                }
        }
}

// ---------------- flash: pipelined scores (AC + strip BD) + exp + PV --------------
__global__ __launch_bounds__(256) void flash_mma()
{
    const int gg = blockIdx.y;
    const int bi = 7 - blockIdx.x;            // heavy CTAs first
    const int i0 = bi << 7;

    extern __shared__ char smr[];
    __half* Qs = (__half*)smr;

    const int tid = threadIdx.x;
    const int warp = tid >> 5, lane = tid & 31;
    const int gq = lane >> 2, tq = lane & 3;
    const int sel = lane >> 3, l7 = lane & 7;
    const int wm = warp << 4;

    const unsigned base = smem_u32(smr);
    const unsigned offA = (((sel&1)*8 + l7)*SROW + (sel>>1)*8)*2;
    const unsigned offB = (((sel>>1)*8 + l7)*SROW + (sel&1)*8)*2;
    const unsigned qsA = base + wm*SROWB + offA;
    const float* vrrow = g_vr + (size_t)gg*TT;

    const int sr = tid >> 1, cb = (tid & 1) * 32;
    const int jt_max = bi + 8;

    // ---- prologue ----
    flash_issue(smr, 0, gg, 0,   (8-bi)<<7, sr, cb, tid);
    asm volatile("cp.async.commit_group;");
    flash_issue(smr, 1, gg, 128, (9-bi)<<7, sr, cb, tid);
    asm volatile("cp.async.commit_group;");
    {   // direct-stage Q and R strip S(0) into BD1 region (temp)
        const __half* qrow = g_q + (((size_t)gg*LQ + i0 + sr) << 6) + cb;
        __half* Rtmp = (__half*)(smr + BD_O(1));
        const int ps0 = (7 - bi) << 7;
        const __half* rrow = g_r + (((size_t)gg*TT + ps0 + sr) << 6) + cb;
        #pragma unroll
        for (int q=0;q<4;q++){
            *(uint4*)&Qs[sr*SROW + cb + q*8]   = *(const uint4*)(qrow + q*8);
            *(uint4*)&Rtmp[sr*SROW + cb + q*8] = *(const uint4*)(rrow + q*8);
        }
        __syncthreads();
        compute_strip_f16(base, base + BD_O(1), (__half*)(smr + BD_O(0)),
                          vrrow, ps0, warp, lane);
    }

    float acc_pv[8][4];
    #pragma unroll
    for (int ni=0;ni<8;ni++)
        #pragma unroll
        for (int c=0;c<4;c++) acc_pv[ni][c]=0.f;
    float rs_0 = 0.f, rs_1 = 0.f;

    for (int jt=0; jt<=jt_max; jt++){
        const int j0 = jt << 7;
        const int s = jt & 1;
        if (jt < jt_max) asm volatile("cp.async.wait_group 1;");
        else             asm volatile("cp.async.wait_group 0;");
        __syncthreads();                       // SYNCa: tile data + strip stores/reads settled

        // AC = Q.K^T
        float acc[16][4];
        #pragma unroll
        for (int ni=0;ni<16;ni++)
            #pragma unroll
            for (int c=0;c<4;c++) acc[ni][c]=0.f;
        const unsigned ksB = base + KS_O(s) + offB;
        #pragma unroll
        for (int kk=0;kk<64;kk+=16){
            unsigned a0,a1,a2,a3;
            ldsm4(a0,a1,a2,a3, qsA + kk*2);
            #pragma unroll
            for (int q=0;q<8;q++){
                unsigned b0,b1,b2,b3;
                ldsm4(b0,b1,b2,b3, ksB + q*2304 + kk*2);
                mma_f16(acc[2*q  ], a0,a1,a2,a3, b0,b1);
                mma_f16(acc[2*q+1], a0,a1,a2,a3, b2,b3);
            }
        }
        // strip for tile jt+1 (and second half of tile jt)
        if (jt < jt_max)
            compute_strip_f16(base, base + RS_O(s), (__half*)(smr + BD_O((jt+1)&1)),
                              vrrow, (jt-bi+8)<<7, warp, lane);
        __syncthreads();                       // SYNCb: strip stores visible

        // gather + exp + mask + write p + row sums
        const bool isDiag = (jt == jt_max);
        const __half* BDa = (const __half*)(smr + BD_O(jt&1));
        const __half* BDb = (const __half*)(smr + BD_O((jt+1)&1));
        const float* uks = (const float*)(smr + UK_O(s));
        const int il0 = wm + gq, il1 = il0 + 8;
        unsigned pfrag[16][2];
        __half* prow0 = g_p + ((size_t)gg*LQ + i0 + il0)*TT + j0;
        __half* prow1 = g_p + ((size_t)gg*LQ + i0 + il1)*TT + j0;
        #pragma unroll
        for (int ni=0;ni<16;ni++){
            const int jl = ni*8 + 2*tq;
            const int o00 = jl - il0 + 127;
            const int o10 = jl - il1 + 127;
            float bd00 = __half2float((o00   < 128) ? BDa[il0*BDSH + o00    ] : BDb[il0*BDSH + o00-128]);
            float bd01 = __half2float((o00+1 < 128) ? BDa[il0*BDSH + o00 + 1] : BDb[il0*BDSH + o00-127]);
            float bd10 = __half2float((o10   < 128) ? BDa[il1*BDSH + o10    ] : BDb[il1*BDSH + o10-128]);
            float bd11 = __half2float((o10+1 < 128) ? BDa[il1*BDSH + o10 + 1] : BDb[il1*BDSH + o10-127]);
            const float u0 = uks[jl], u1 = uks[jl+1];
            float p0 = __expf((acc[ni][0] + bd00 + u0)*SCALE_F - EXPC);
            float p1 = __expf((acc[ni][1] + bd01 + u1)*SCALE_F - EXPC);
            float p2 = __expf((acc[ni][2] + bd10 + u0)*SCALE_F - EXPC);
            float p3 = __expf((acc[ni][3] + bd11 + u1)*SCALE_F - EXPC);
            if (isDiag){
                if (jl   > il0) p0 = 0.f;
                if (jl+1 > il0) p1 = 0.f;
                if (jl   > il1) p2 = 0.f;
                if (jl+1 > il1) p3 = 0.f;
            }
            rs_0 += p0 + p1;
            rs_1 += p2 + p3;
            unsigned lo = pack_h2(p0, p1), hi = pack_h2(p2, p3);
            *reinterpret_cast<unsigned*>(prow0 + jl) = lo;
            *reinterpret_cast<unsigned*>(prow1 + jl) = hi;
            pfrag[ni][0] = lo;
            pfrag[ni][1] = hi;
        }
        // PV
        const unsigned vsB = base + VS_O(s) + offA;
        #pragma unroll
        for (int t8=0;t8<8;t8++){
            unsigned a0 = pfrag[2*t8][0], a1 = pfrag[2*t8][1];
            unsigned a2 = pfrag[2*t8+1][0], a3 = pfrag[2*t8+1][1];
            #pragma unroll
            for (int q=0;q<4;q++){
                unsigned b0,b1,b2,b3;
                ldsm4t(b0,b1,b2,b3, vsB + t8*2304 + q*32);
                mma_f16(acc_pv[2*q  ], a0,a1,a2,a3, b0,b1);
                mma_f16(acc_pv[2*q+1], a0,a1,a2,a3, b2,b3);
            }
        }
        __syncthreads();                       // SYNCc: buf s free for refill
        if (jt + 2 <= jt_max){
            flash_issue(smr, s, gg, (jt+2)<<7, (jt+2-bi+8)<<7, sr, cb, tid);
            asm volatile("cp.async.commit_group;");
        }
    }

    // epilogue
    rs_0 += __shfl_xor_sync(0xffffffffu, rs_0, 1);
    rs_0 += __shfl_xor_sync(0xffffffffu, rs_0, 2);
    rs_1 += __shfl_xor_sync(0xffffffffu, rs_1, 1);
    rs_1 += __shfl_xor_sync(0xffffffffu, rs_1, 2);
    const int row0 = i0 + wm + gq, row1 = row0 + 8;
    if (tq == 0){
        g_rs[gg*LQ + row0] = rs_0;
        g_rs[gg*LQ + row1] = rs_1;
    }
    const float inv0 = 1.f / rs_0, inv1 = 1.f / rs_1;
    const int b = gg >> 4, h = gg & (NH-1);
    __half* dst0 = g_av + (size_t)(row0*BATCH + b)*DMODEL + (h<<6);
    __half* dst1 = g_av + (size_t)(row1*BATCH + b)*DMODEL + (h<<6);
    #pragma unroll
    for (int ni=0;ni<8;ni++){
        const int d = ni*8 + 2*tq;
        *reinterpret_cast<unsigned*>(dst0 + d) = pack_h2(acc_pv[ni][0]*inv0, acc_pv[ni][1]*inv0);
        *reinterpret_cast<unsigned*>(dst1 + d) = pack_h2(acc_pv[ni][2]*inv1, acc_pv[ni][3]*inv1);
    }
}

// ---------------- attn_matrix = mean over (b,h) of p/rs --------------------------
__global__ __launch_bounds__(256) void attnmat_kernel(float* __restrict__ out)
{
    const int i  = blockIdx.y;
    const int j0 = blockIdx.x << 9;
    const int jmax = i + MEMLEN;
    const int tid = threadIdx.x;
    const int jq = tid & 63;
    const int gsel = tid >> 6;
    const int j = j0 + jq*8;
    __shared__ float red[256][9];

    float a[8] = {0.f,0.f,0.f,0.f,0.f,0.f,0.f,0.f};
    if (j0 <= jmax){
        #pragma unroll
        for (int gi=0; gi<8; gi++){
            int g = gsel*8 + gi;
            float inv = 1.f / g_rs[g*LQ + i];
            uint4 raw = *(const uint4*)(g_p + ((size_t)g*LQ + i)*TT + j);
            const __half2* hp = (const __half2*)&raw;
            #pragma unroll
            for (int e=0;e<4;e++){
                float2 f = __half22float2(hp[e]);
                a[2*e]   += f.x * inv;
                a[2*e+1] += f.y * inv;
            }
        }
        #pragma unroll
        for (int e=0;e<8;e++) if (j+e > jmax) a[e] = 0.f;
    }
    #pragma unroll
    for (int e=0;e<8;e++) red[tid][e] = a[e];
    __syncthreads();
    if (tid < 64){
        const float k = 1.f/NG;
        float o[8];
        #pragma unroll
        for (int e=0;e<8;e++)
            o[e] = (red[tid][e] + red[tid+64][e] + red[tid+128][e] + red[tid+192][e]) * k;
        float* dst = out + (size_t)i*TT + j0 + tid*8;
        *(float4*)dst     = make_float4(o[0],o[1],o[2],o[3]);
        *(float4*)(dst+4) = make_float4(o[4],o[5],o[6],o[7]);
    }
}

// ---------------- Wo GEMM + residual (fp16 MMA): g_h = x + g_av @ Wo ------------
__global__ __launch_bounds__(256) void wo_mma(const float* __restrict__ x)
{
    const int m0 = blockIdx.y << 7;
    const int n0 = blockIdx.x << 6;

    __shared__ __half   As[128*40];
    __shared__ unsigned Bs[16*72];

    const int tid = threadIdx.x;
    const int warp = tid >> 5, lane = tid & 31;
    const int gq = lane >> 2, tq = lane & 3;
    const int wm = (warp >> 1) * 32, wn = (warp & 1) * 32;
    const unsigned* As2 = (const unsigned*)As;

    float acc[2][4][4];
    #pragma unroll
    for (int mi=0;mi<2;mi++)
        #pragma unroll
        for (int ni=0;ni<4;ni++)
            #pragma unroll
            for (int c=0;c<4;c++) acc[mi][ni][c]=0.f;

    const int a_r = tid >> 1;
    const int a_cb = (tid & 1) * 16;
    const __half* arow = g_av + (size_t)(m0 + a_r)*DMODEL + a_cb;
    const int b_k2 = tid >> 4;
    const int b_cb = (tid & 15) * 4;

    for (int k0=0;k0<DMODEL;k0+=32){
        {
            __half* Ad = As + a_r*40 + a_cb;
            *(uint4*)Ad     = *(const uint4*)(arow + k0);
            *(uint4*)(Ad+8) = *(const uint4*)(arow + k0 + 8);
            const unsigned* bsrc = g_woi + (size_t)((k0>>1) + b_k2)*DMODEL + n0 + b_cb;
            *(uint4*)&Bs[b_k2*72 + b_cb] = *(const uint4*)bsrc;
        }
        __syncthreads();
        #pragma unroll
        for (int kk=0;kk<32;kk+=16){
            const int k2 = kk >> 1;
            unsigned a[2][4], bfr[4][2];
            #pragma unroll
            for (int mi=0;mi<2;mi++){
                int m = wm + mi*16;
                a[mi][0] = As2[(m+gq  )*20 + k2 + tq  ];
                a[mi][1] = As2[(m+gq+8)*20 + k2 + tq  ];
                a[mi][2] = As2[(m+gq  )*20 + k2 + tq+4];
                a[mi][3] = As2[(m+gq+8)*20 + k2 + tq+4];
            }
            #pragma unroll
            for (int ni=0;ni<4;ni++){
                int n = wn + ni*8 + gq;
                bfr[ni][0] = Bs[(k2+tq  )*72 + n];
                bfr[ni][1] = Bs[(k2+tq+4)*72 + n];
            }
            #pragma unroll
            for (int mi=0;mi<2;mi++)
                #pragma unroll
                for (int ni=0;ni<4;ni++)
                    mma_f16(acc[mi][ni], a[mi][0],a[mi][1],a[mi][2],a[mi][3], bfr[ni][0],bfr[ni][1]);
        }
        __syncthreads();
    }

    #pragma unroll
    for (int mi=0;mi<2;mi++)
        #pragma unroll
        for (int rr=0;rr<2;rr++){
            const int row = m0 + wm + mi*16 + gq + rr*8;
            #pragma unroll
            for (int ni=0;ni<4;ni++){
                const int col = n0 + wn + ni*8 + 2*tq;
                float2 xv = *(const float2*)&x[(size_t)row*DMODEL + col];
                float2 val = { acc[mi][ni][rr*2+0] + xv.x,
                               acc[mi][ni][rr*2+1] + xv.y };
                *(float2*)&g_h[(size_t)row*DMODEL + col] = val;
            }
        }
}

// ---------------- layernorm ------------------------------------------------------
__global__ __launch_bounds__(256) void ln_kernel(const float* __restrict__ gamma,
                                                 const float* __restrict__ beta,
                                                 float* __restrict__ out)
{
    const int row = blockIdx.x;
    const float* hr = g_h + (size_t)row*DMODEL;
    const int c = threadIdx.x * 4;
    float4 v = *(const float4*)(hr + c);
    float s = v.x+v.y+v.z+v.w;
    s = blockSum(s);
    const float mu = s * (1.f/DMODEL);
    float dx = v.x-mu, dy = v.y-mu, dz = v.z-mu, dw = v.w-mu;
    float sq = dx*dx+dy*dy+dz*dz+dw*dw;
    sq = blockSum(sq);
    const float inv = rsqrtf(sq*(1.f/DMODEL) + 1e-5f);
    float4 gm = *(const float4*)(gamma + c);
    float4 bt = *(const float4*)(beta + c);
    float4 o;
    o.x = dx*inv*gm.x + bt.x;
    o.y = dy*inv*gm.y + bt.y;
    o.z = dz*inv*gm.z + bt.z;
    o.w = dw*inv*gm.w + bt.w;
    *(float4*)(out + (size_t)row*DMODEL + c) = o;
}

// ---------------- launch ----------------------------------------------------------
extern "C" void kernel_launch(void* const* d_in, const int* in_sizes, int n_in,
                              void* d_out, int out_size)
{
    const float* x        = (const float*)d_in[0];
    const float* pos_emb  = (const float*)d_in[1];
    const float* memory   = (const float*)d_in[2];
    const float* ubias    = (const float*)d_in[3];
    const float* vbias    = (const float*)d_in[4];
    const float* Wq       = (const float*)d_in[6];
    const float* Wkv      = (const float*)d_in[7];
    const float* Wrel     = (const float*)d_in[8];
    const float* Wo       = (const float*)d_in[9];
    const float* gamma    = (const float*)d_in[10];
    const float* beta     = (const float*)d_in[11];
    float* out    = (float*)d_out;
    float* out_am = out + (size_t)LQ*BATCH*DMODEL;

    cudaFuncSetAttribute(flash_mma, cudaFuncAttributeMaxDynamicSharedMemorySize, FL_SMEM_BYTES);
    cudaFuncSetAttribute(qkvr_mma,  cudaFuncAttributeMaxDynamicSharedMemorySize, QK_SMEM_BYTES);

    cvt_all<<<5632, 256>>>(x, memory, pos_emb, Wq, Wkv, Wrel, Wo);
    qkvr_mma<<<896, 256, QK_SMEM_BYTES>>>();
    ukvr_kernel<<<dim3(TT/32, NG), 256>>>(ubias, vbias);
    flash_mma<<<dim3(8, NG), 256, FL_SMEM_BYTES>>>();
    attnmat_kernel<<<dim3(4, LQ), 256>>>(out_am);
    wo_mma<<<dim3(16,16), 256>>>(x);
    ln_kernel<<<LQ*BATCH, 256>>>(gamma, beta, out);
}

// round 16
// speedup vs baseline: 1.3016x; 1.0439x over previous
#include <cuda_runtime.h>
#include <cuda_fp16.h>
#include <math.h>
#include <stdint.h>

#define LQ      1024
#define BATCH   2
#define DMODEL  1024
#define NH      16
#define DHD     64
#define MEMLEN  1024
#define TT      2048
#define NG      (BATCH*NH)
#define SCALE_F 0.125f
#define EXPC    8.0f
#define SROW    72          // halves per staged row
#define SROWB   144         // bytes per staged row
#define BDSH    136         // halves per fp16 BD strip row

// ---------------- scratch -------------------------------------------------------
__device__ __half g_q [NG*LQ*DHD];
__device__ __half g_k [NG*TT*DHD];
__device__ __half g_v [NG*TT*DHD];
__device__ __half g_r [NG*TT*DHD];
__device__ __half g_p [(size_t)NG*LQ*TT];            // unnormalized e^(s-8) (fp16)
__device__ float  g_rs[NG*LQ];                       // row sums of e^(s-8)
__device__ float  g_uk[NG*TT];                       // u . k_t
__device__ float  g_vr[NG*TT];                       // v . r_t
__device__ __half g_av[LQ*BATCH*NH*DHD];
__device__ float  g_h [LQ*BATCH*DMODEL];
// fp16 pre-converted inputs / weights
__device__ __half   g_xh   [LQ*BATCH*DMODEL];
__device__ __half   g_memh [MEMLEN*BATCH*DMODEL];
__device__ __half   g_posh [TT*BATCH*DMODEL];
__device__ __half   g_wqt  [1024*1024];              // W^T [n][k] fp16
__device__ __half   g_wkvt [2048*1024];
__device__ __half   g_wrelt[1024*1024];
__device__ unsigned g_woi  [512*1024];               // (W[2k],W[2k+1]) half2 pairs (wo)

// ---------------- helpers ---------------------------------------------------------
__device__ __forceinline__ unsigned pack_h2(float a, float b){
    __half2 h = __floats2half2_rn(a, b);
    return *reinterpret_cast<unsigned*>(&h);
}
__device__ __forceinline__ void mma_f16(float c[4],
                                        unsigned a0, unsigned a1, unsigned a2, unsigned a3,
                                        unsigned b0, unsigned b1){
    asm volatile("mma.sync.aligned.m16n8k16.row.col.f32.f16.f16.f32 "
        "{%0,%1,%2,%3}, {%4,%5,%6,%7}, {%8,%9}, {%0,%1,%2,%3};"
        : "+f"(c[0]), "+f"(c[1]), "+f"(c[2]), "+f"(c[3])
        : "r"(a0), "r"(a1), "r"(a2), "r"(a3), "r"(b0), "r"(b1));
}
__device__ __forceinline__ unsigned smem_u32(const void* p){
    return (unsigned)__cvta_generic_to_shared(p);
}
__device__ __forceinline__ void ldsm4(unsigned &r0, unsigned &r1, unsigned &r2, unsigned &r3, unsigned a){
    asm volatile("ldmatrix.sync.aligned.m8n8.x4.shared.b16 {%0,%1,%2,%3}, [%4];"
        : "=r"(r0),"=r"(r1),"=r"(r2),"=r"(r3) : "r"(a));
}
__device__ __forceinline__ void ldsm4t(unsigned &r0, unsigned &r1, unsigned &r2, unsigned &r3, unsigned a){
    asm volatile("ldmatrix.sync.aligned.m8n8.x4.trans.shared.b16 {%0,%1,%2,%3}, [%4];"
        : "=r"(r0),"=r"(r1),"=r"(r2),"=r"(r3) : "r"(a));
}
__device__ __forceinline__ void cpasync16(unsigned dst, const void* src){
    asm volatile("cp.async.cg.shared.global [%0], [%1], 16;" :: "r"(dst), "l"(src));
}

__device__ __forceinline__ float blockSum(float v){
    __shared__ float sm[32];
    int lane = threadIdx.x & 31, w = threadIdx.x >> 5;
    #pragma unroll
    for (int o=16;o>0;o>>=1) v += __shfl_xor_sync(0xffffffffu, v, o);
    if (lane==0) sm[w] = v;
    __syncthreads();
    float r = (threadIdx.x < 8) ? sm[threadIdx.x] : 0.f;
    if (w==0){
        #pragma unroll
        for (int o=4;o>0;o>>=1) r += __shfl_xor_sync(0xffffffffu, r, o);
        if (lane==0) sm[0]=r;
    }
    __syncthreads();
    r = sm[0];
    __syncthreads();
    return r;
}

// ---------------- fp16 pre-conversion -------------------------------------------
__device__ __forceinline__ void cvt_plain(const float* __restrict__ s, __half* d, int b, int t){
    const int idx = b*2048 + t*8;
    float4 v0 = *(const float4*)(s+idx), v1 = *(const float4*)(s+idx+4);
    unsigned u[4] = { pack_h2(v0.x,v0.y), pack_h2(v0.z,v0.w),
                      pack_h2(v1.x,v1.y), pack_h2(v1.z,v1.w) };
    *(uint4*)&d[idx] = *(uint4*)u;
}
__device__ __forceinline__ void cvt_inter(const float* __restrict__ W, unsigned* d,
                                          int b, int t, int lgN){
    const int p = b*1024 + t*4;
    const int N = 1 << lgN;
    const int k2 = p >> lgN, n = p & (N-1);
    const float* r0 = W + ((size_t)k2*2)*N + n;
    float4 a = *(const float4*)r0;
    float4 c = *(const float4*)(r0 + N);
    unsigned u[4] = { pack_h2(a.x,c.x), pack_h2(a.y,c.y),
                      pack_h2(a.z,c.z), pack_h2(a.w,c.w) };
    *(uint4*)&d[p] = *(uint4*)u;
}
__device__ void cvt_wt_tile(const float* __restrict__ W, __half* Wt, int N,
                            int ky, int nx, int tid){
    __shared__ float buf[64][65];
    const int k0 = ky*64, n0c = nx*64;
    const int kr = tid>>2, nc = (tid&3)*16;
    #pragma unroll
    for (int q=0;q<4;q++){
        float4 w = *(const float4*)(W + (size_t)(k0+kr)*N + n0c + nc + q*4);
        buf[kr][nc+q*4+0]=w.x; buf[kr][nc+q*4+1]=w.y;
        buf[kr][nc+q*4+2]=w.z; buf[kr][nc+q*4+3]=w.w;
    }
    __syncthreads();
    const int nr = tid>>2, kc = (tid&3)*16;
    unsigned u[8];
    #pragma unroll
    for (int e=0;e<8;e++)
        u[e] = pack_h2(buf[kc+2*e][nr], buf[kc+2*e+1][nr]);
    __half* dst = Wt + (size_t)(n0c+nr)*1024 + k0 + kc;
    *(uint4*)dst     = *(uint4*)&u[0];
    *(uint4*)(dst+8) = *(uint4*)&u[4];
}
__global__ __launch_bounds__(256) void cvt_all(const float* __restrict__ x,
                                               const float* __restrict__ memory,
                                               const float* __restrict__ pos_emb,
                                               const float* __restrict__ Wq,
                                               const float* __restrict__ Wkv,
                                               const float* __restrict__ Wrel,
                                               const float* __restrict__ Wo)
{
    const int bid = blockIdx.x, tid = threadIdx.x;
    if      (bid < 1024) cvt_plain(x,       g_xh,   bid,        tid);
    else if (bid < 2048) cvt_plain(memory,  g_memh, bid-1024,   tid);
    else if (bid < 4096) cvt_plain(pos_emb, g_posh, bid-2048,   tid);
    else if (bid < 4608) cvt_inter(Wo, g_woi, bid-4096, tid, 10);
    else {
        int t = bid - 4608;
        if (t < 256)      cvt_wt_tile(Wq,   g_wqt,   1024, t>>4,        t&15,        tid);
        else if (t < 768) cvt_wt_tile(Wkv,  g_wkvt,  2048, (t-256)>>5,  (t-256)&31,  tid);
        else              cvt_wt_tile(Wrel, g_wrelt, 1024, (t-768)>>4,  (t-768)&15,  tid);
    }
}

// ---------------- uk/vr precompute -----------------------------------------------
__global__ __launch_bounds__(256) void ukvr_kernel(const float* __restrict__ ubias,
                                                   const float* __restrict__ vbias)
{
    const int g = blockIdx.y, h = g & (NH-1);
    const int tid = threadIdx.x;
    const int which = tid >> 7;
    const int sub = tid & 127;
    const int t = blockIdx.x*32 + (sub >> 2);
    const int rq = sub & 3;
    const __half* src = (which ? g_r : g_k) + (((size_t)g*TT + t) << 6) + rq*16;
    const float* bs = (which ? vbias : ubias) + (h << 6) + rq*16;
    uint4 u0 = *(const uint4*)src, u1 = *(const uint4*)(src + 8);
    const __half* h0 = (const __half*)&u0;
    const __half* h1 = (const __half*)&u1;
    float s = 0.f;
    #pragma unroll
    for (int e=0;e<8;e++) s += __half2float(h0[e]) * bs[e];
    #pragma unroll
    for (int e=0;e<8;e++) s += __half2float(h1[e]) * bs[8+e];
    s += __shfl_xor_sync(0xffffffffu, s, 1);
    s += __shfl_xor_sync(0xffffffffu, s, 2);
    if (rq == 0) (which ? g_vr : g_uk)[g*TT + t] = s;
}

// ---------------- QKVR projection GEMM (fp16 MMA, cp.async double-buffered) ------
#define QK_SMEM_BYTES (4*128*SROW*2)

__device__ __forceinline__ void qkvr_store(int mode, int row, int col, unsigned hv){
    const int t = row >> 1, bb = row & 1;
    if (mode==0){
        int h = col >> 6, d = col & 63;
        *reinterpret_cast<unsigned*>(&g_q[(((size_t)(bb*NH+h)*LQ + t)<<6) + d]) = hv;
    } else if (mode==1){
        int c2 = col; __half* dst = g_k;
        if (c2 >= NH*DHD){ dst = g_v; c2 -= NH*DHD; }
        int h = c2 >> 6, d = c2 & 63;
        *reinterpret_cast<unsigned*>(&dst[(((size_t)(bb*NH+h)*TT + t)<<6) + d]) = hv;
    } else {
        int h = col >> 6, d = col & 63;
        *reinterpret_cast<unsigned*>(&g_r[(((size_t)(bb*NH+h)*TT + t)<<6) + d]) = hv;
    }
}

__global__ __launch_bounds__(256) void qkvr_mma()
{
    extern __shared__ __half smqk[];
    __half* Asb[2] = { smqk,              smqk +   128*SROW };
    __half* Bsb[2] = { smqk + 2*128*SROW, smqk + 3*128*SROW };

    int bid = blockIdx.x;
    int mode, m0, n0;
    const __half* Wt;
    if (bid < 128)      { mode=0; m0=(bid>>3)<<7;  n0=(bid&7)<<7;  Wt=g_wqt;  }
    else if (bid < 640) { int t=bid-128; mode=1; m0=(t>>4)<<7; n0=(t&15)<<7; Wt=g_wkvt; }
    else                { int t=bid-640; mode=2; m0=(t>>3)<<7; n0=(t&7)<<7;  Wt=g_wrelt;}

    const int tid = threadIdx.x;
    const int warp = tid >> 5, lane = tid & 31;
    const int gq = lane >> 2, tq = lane & 3;
    const int sel = lane >> 3, l7 = lane & 7;
    const int wm = warp << 4;

    const unsigned offA = (((sel&1)*8 + l7)*SROW + (sel>>1)*8)*2;
    const unsigned offB = (((sel>>1)*8 + l7)*SROW + (sel&1)*8)*2;
    const int sr = tid >> 1, cb = (tid & 1) * 32;
    unsigned asA[2], bsB[2], adst[2], bdst[2];
    #pragma unroll
    for (int s=0;s<2;s++){
        asA[s]  = smem_u32(Asb[s]) + wm*SROWB + offA;
        bsB[s]  = smem_u32(Bsb[s]) + offB;
        adst[s] = smem_u32(Asb[s]) + (sr*SROW + cb)*2;
        bdst[s] = smem_u32(Bsb[s]) + (sr*SROW + cb)*2;
    }

    const __half* arow;
    {
        int grow = m0 + sr;
        if (mode==0)      arow = g_xh + (size_t)grow*DMODEL;
        else if (mode==1) arow = (grow < MEMLEN*BATCH) ? g_memh + (size_t)grow*DMODEL
                                                       : g_xh + (size_t)(grow - MEMLEN*BATCH)*DMODEL;
        else              arow = g_posh + (size_t)grow*DMODEL;
    }
    const __half* brow = Wt + (size_t)(n0 + sr)*DMODEL;

    #pragma unroll
    for (int q=0;q<4;q++){
        cpasync16(adst[0] + q*16, arow + cb + q*8);
        cpasync16(bdst[0] + q*16, brow + cb + q*8);
    }
    asm volatile("cp.async.commit_group;");
    asm volatile("cp.async.wait_group 0;");
    __syncthreads();

    float acc[16][4];
    #pragma unroll
    for (int ni=0;ni<16;ni++)
        #pragma unroll
        for (int c=0;c<4;c++) acc[ni][c]=0.f;

    for (int c=0;c<16;c++){
        const int s = c & 1;
        if (c < 15){
            const __half* asrc = arow + (c+1)*64 + cb;
            const __half* bsrc = brow + (c+1)*64 + cb;
            #pragma unroll
            for (int q=0;q<4;q++){
                cpasync16(adst[s^1] + q*16, asrc + q*8);
                cpasync16(bdst[s^1] + q*16, bsrc + q*8);
            }
            asm volatile("cp.async.commit_group;");
        }
        #pragma unroll
        for (int kk=0;kk<64;kk+=16){
            unsigned a0,a1,a2,a3;
            ldsm4(a0,a1,a2,a3, asA[s] + kk*2);
            #pragma unroll
            for (int q=0;q<8;q++){
                unsigned b0,b1,b2,b3;
                ldsm4(b0,b1,b2,b3, bsB[s] + q*2304 + kk*2);
                mma_f16(acc[2*q  ], a0,a1,a2,a3, b0,b1);
                mma_f16(acc[2*q+1], a0,a1,a2,a3, b2,b3);
            }
        }
        if (c < 15)
            asm volatile("cp.async.wait_group 0;");
        __syncthreads();
    }

    const int row0 = m0 + wm + gq, row1 = row0 + 8;
    #pragma unroll
    for (int ni=0;ni<16;ni++){
        const int col = n0 + ni*8 + 2*tq;
        qkvr_store(mode, row0, col, pack_h2(acc[ni][0], acc[ni][1]));
        qkvr_store(mode, row1, col, pack_h2(acc[ni][2], acc[ni][3]));
    }
}

// ---------------- flash SMEM layout ------------------------------------------------
#define KS_O(s)  (18432 + (s)*18432)
#define RS_O(s)  (55296 + (s)*18432)
#define VS_O(s)  (92160 + (s)*18432)
#define BD_O(s)  (129024 + (s)*34816)
#define UK_O(s)  (198656 + (s)*512)
#define FL_SMEM_BYTES 199680

// staging with 512 threads: sr = tid>>2 (row), cb = (tid&3)*16 (halves), 2 x 16B
__device__ __forceinline__ void flash_issue(char* smr, int s, int gg, int j0, int ps,
                                            int sr, int cb, int tid){
    const __half* krow = g_k + (((size_t)gg*TT + j0 + sr) << 6) + cb;
    const __half* vrow = g_v + (((size_t)gg*TT + j0 + sr) << 6) + cb;
    const int rg = min(ps + sr, TT-1);
    const __half* rrow = g_r + (((size_t)gg*TT + rg) << 6) + cb;
    const unsigned base = smem_u32(smr);
    const unsigned off = (sr*SROW + cb)*2;
    const unsigned kd = base + KS_O(s) + off;
    const unsigned rd = base + RS_O(s) + off;
    const unsigned vd = base + VS_O(s) + off;
    #pragma unroll
    for (int q=0;q<2;q++){
        cpasync16(kd + q*16, krow + q*8);
        cpasync16(vd + q*16, vrow + q*8);
        cpasync16(rd + q*16, rrow + q*8);
    }
    if (tid < 32)
        cpasync16(base + UK_O(s) + tid*16, g_uk + (size_t)gg*TT + j0 + tid*4);
}

// ---------------- BD strip (16 warps: 32x32 sub-tiles, fp16 out, vr folded) ------
__device__ __forceinline__ void compute_strip_f16(unsigned qs_u32, unsigned rs_base,
                                                  __half* BDslot, const float* vrrow,
                                                  int pstrip, int warp, int lane)
{
    const int sel = lane >> 3, l7 = lane & 7;
    const int gq = lane >> 2, tq = lane & 3;
    const int wmb = (warp >> 2) * 32, wnb = (warp & 3) * 32;
    const unsigned offA = (((sel&1)*8 + l7)*SROW + (sel>>1)*8)*2;
    const unsigned offB = (((sel>>1)*8 + l7)*SROW + (sel&1)*8)*2;
    const unsigned rs_u32 = rs_base + offB;

    float abd[2][4][4];
    #pragma unroll
    for (int mi=0;mi<2;mi++)
        #pragma unroll
        for (int ni=0;ni<4;ni++)
            #pragma unroll
            for (int e=0;e<4;e++) abd[mi][ni][e]=0.f;
    #pragma unroll
    for (int kk=0;kk<64;kk+=16){
        unsigned am[2][4];
        #pragma unroll
        for (int mi=0;mi<2;mi++)
            ldsm4(am[mi][0],am[mi][1],am[mi][2],am[mi][3],
                  qs_u32 + (wmb + mi*16)*SROWB + offA + kk*2);
        #pragma unroll
        for (int q=0;q<2;q++){
            unsigned b0,b1,b2,b3;
            ldsm4(b0,b1,b2,b3, rs_u32 + (wnb + 16*q)*SROWB + kk*2);
            mma_f16(abd[0][2*q  ], am[0][0],am[0][1],am[0][2],am[0][3], b0,b1);
            mma_f16(abd[0][2*q+1], am[0][0],am[0][1],am[0][2],am[0][3], b2,b3);
            mma_f16(abd[1][2*q  ], am[1][0],am[1][1],am[1][2],am[1][3], b0,b1);
            mma_f16(abd[1][2*q+1], am[1][0],am[1][1],am[1][2],am[1][3], b2,b3);
        }
    }
    #pragma unroll
    for (int ni=0;ni<4;ni++){
        const int pl = wnb + ni*8 + 2*tq;
        const float vr0 = vrrow[min(pstrip + pl,     TT-1)];
        const float vr1 = vrrow[min(pstrip + pl + 1, TT-1)];
        #pragma unroll
        for (int mi=0;mi<2;mi++)
            #pragma unroll
            for (int rr=0;rr<2;rr++){
                const int il = wmb + mi*16 + gq + rr*8;
                *reinterpret_cast<unsigned*>(&BDslot[il*BDSH + pl]) =
                    pack_h2(abd[mi][ni][rr*2+0] + vr0,
                            abd[mi][ni][rr*2+1] + vr1);
            }
    }
}

// ---------------- flash: 512 threads, warp pair splits j ---------------------------
__global__ __launch_bounds__(512) void flash_mma()
{
    const int gg = blockIdx.y;
    const int bi = 7 - blockIdx.x;            // heavy CTAs first
    const int i0 = bi << 7;

    extern __shared__ char smr[];
    __half* Qs = (__half*)smr;

    const int tid = threadIdx.x;
    const int warp = tid >> 5, lane = tid & 31;
    const int gq = lane >> 2, tq = lane & 3;
    const int sel = lane >> 3, l7 = lane & 7;
    const int rg = warp >> 1, jh = warp & 1;
    const int wm = rg << 4;
    const int jbase = jh << 6;

    const unsigned base = smem_u32(smr);
    const unsigned offA = (((sel&1)*8 + l7)*SROW + (sel>>1)*8)*2;
    const unsigned offB = (((sel>>1)*8 + l7)*SROW + (sel&1)*8)*2;
    const unsigned qsA = base + wm*SROWB + offA;
    const float* vrrow = g_vr + (size_t)gg*TT;

    const int sr = tid >> 2, cb = (tid & 3) * 16;
    const int jt_max = bi + 8;

    // ---- prologue ----
    flash_issue(smr, 0, gg, 0,   (8-bi)<<7, sr, cb, tid);
    asm volatile("cp.async.commit_group;");
    flash_issue(smr, 1, gg, 128, (9-bi)<<7, sr, cb, tid);
    asm volatile("cp.async.commit_group;");
    {
        const __half* qrow = g_q + (((size_t)gg*LQ + i0 + sr) << 6) + cb;
        __half* Rtmp = (__half*)(smr + BD_O(1));
        const int ps0 = (7 - bi) << 7;
        const __half* rrow = g_r + (((size_t)gg*TT + min(ps0 + sr, TT-1)) << 6) + cb;
        #pragma unroll
        for (int q=0;q<2;q++){
            *(uint4*)&Qs[sr*SROW + cb + q*8]   = *(const uint4*)(qrow + q*8);
            *(uint4*)&Rtmp[sr*SROW + cb + q*8] = *(const uint4*)(rrow + q*8);
        }
        __syncthreads();
        compute_strip_f16(base, base + BD_O(1), (__half*)(smr + BD_O(0)),
                          vrrow, ps0, warp, lane);
    }

    float acc_pv[8][4];
    #pragma unroll
    for (int ni=0;ni<8;ni++)
        #pragma unroll
        for (int c=0;c<4;c++) acc_pv[ni][c]=0.f;
    float rs_0 = 0.f, rs_1 = 0.f;

    for (int jt=0; jt<=jt_max; jt++){
        const int j0 = jt << 7;
        const int s = jt & 1;
        if (jt < jt_max) asm volatile("cp.async.wait_group 1;");
        else             asm volatile("cp.async.wait_group 0;");
        __syncthreads();                       // SYNCa

        // AC = Q.K^T (16 rows x 64 cols per warp)
        float acc[8][4];
        #pragma unroll
        for (int ni=0;ni<8;ni++)
            #pragma unroll
            for (int c=0;c<4;c++) acc[ni][c]=0.f;
        const unsigned ksB = base + KS_O(s) + jh*9216 + offB;
        #pragma unroll
        for (int kk=0;kk<64;kk+=16){
            unsigned a0,a1,a2,a3;
            ldsm4(a0,a1,a2,a3, qsA + kk*2);
            #pragma unroll
            for (int q=0;q<4;q++){
                unsigned b0,b1,b2,b3;
                ldsm4(b0,b1,b2,b3, ksB + q*2304 + kk*2);
                mma_f16(acc[2*q  ], a0,a1,a2,a3, b0,b1);
                mma_f16(acc[2*q+1], a0,a1,a2,a3, b2,b3);
            }
        }
        if (jt < jt_max)
            compute_strip_f16(base, base + RS_O(s), (__half*)(smr + BD_O((jt+1)&1)),
                              vrrow, (jt-bi+8)<<7, warp, lane);
        __syncthreads();                       // SYNCb

        // gather + exp + mask + write p + row sums
        const bool isDiag = (jt == jt_max);
        const __half* BDa = (const __half*)(smr + BD_O(jt&1));
        const __half* BDb = (const __half*)(smr + BD_O((jt+1)&1));
        const float* uks = (const float*)(smr + UK_O(s));
        const int il0 = wm + gq, il1 = il0 + 8;
        unsigned pfrag[8][2];
        __half* prow0 = g_p + ((size_t)gg*LQ + i0 + il0)*TT + j0;
        __half* prow1 = g_p + ((size_t)gg*LQ + i0 + il1)*TT + j0;
        #pragma unroll
        for (int ni=0;ni<8;ni++){
            const int jl = jbase + ni*8 + 2*tq;
            const int o00 = jl - il0 + 127;
            const int o10 = jl - il1 + 127;
            float bd00 = __half2float((o00   < 128) ? BDa[il0*BDSH + o00    ] : BDb[il0*BDSH + o00-128]);
            float bd01 = __half2float((o00+1 < 128) ? BDa[il0*BDSH + o00 + 1] : BDb[il0*BDSH + o00-127]);
            float bd10 = __half2float((o10   < 128) ? BDa[il1*BDSH + o10    ] : BDb[il1*BDSH + o10-128]);
            float bd11 = __half2float((o10+1 < 128) ? BDa[il1*BDSH + o10 + 1] : BDb[il1*BDSH + o10-127]);
            const float u0 = uks[jl], u1 = uks[jl+1];
            float p0 = __expf((acc[ni][0] + bd00 + u0)*SCALE_F - EXPC);
            float p1 = __expf((acc[ni][1] + bd01 + u1)*SCALE_F - EXPC);
            float p2 = __expf((acc[ni][2] + bd10 + u0)*SCALE_F - EXPC);
            float p3 = __expf((acc[ni][3] + bd11 + u1)*SCALE_F - EXPC);
            if (isDiag){
                if (jl   > il0) p0 = 0.f;
                if (jl+1 > il0) p1 = 0.f;
                if (jl   > il1) p2 = 0.f;
                if (jl+1 > il1) p3 = 0.f;
            }
            rs_0 += p0 + p1;
            rs_1 += p2 + p3;
            unsigned lo = pack_h2(p0, p1), hi = pack_h2(p2, p3);
            *reinterpret_cast<unsigned*>(prow0 + jl) = lo;
            *reinterpret_cast<unsigned*>(prow1 + jl) = hi;
            pfrag[ni][0] = lo;
            pfrag[ni][1] = hi;
        }
        // PV over this warp's j-half
        const unsigned vsB = base + VS_O(s) + jh*9216 + offA;
        #pragma unroll
        for (int t8=0;t8<4;t8++){
            unsigned a0 = pfrag[2*t8][0], a1 = pfrag[2*t8][1];
            unsigned a2 = pfrag[2*t8+1][0], a3 = pfrag[2*t8+1][1];
            #pragma unroll
            for (int q=0;q<4;q++){
                unsigned b0,b1,b2,b3;
                ldsm4t(b0,b1,b2,b3, vsB + t8*2304 + q*32);
                mma_f16(acc_pv[2*q  ], a0,a1,a2,a3, b0,b1);
                mma_f16(acc_pv[2*q+1], a0,a1,a2,a3, b2,b3);
            }
        }
        __syncthreads();                       // SYNCc
        if (jt + 2 <= jt_max){
            flash_issue(smr, s, gg, (jt+2)<<7, (jt+2-bi+8)<<7, sr, cb, tid);
            asm volatile("cp.async.commit_group;");
        }
    }

    // ---- epilogue: combine j-halves via SMEM, normalize, write ----
    rs_0 += __shfl_xor_sync(0xffffffffu, rs_0, 1);
    rs_0 += __shfl_xor_sync(0xffffffffu, rs_0, 2);
    rs_1 += __shfl_xor_sync(0xffffffffu, rs_1, 1);
    rs_1 += __shfl_xor_sync(0xffffffffu, rs_1, 2);

    float* pvred = (float*)(smr + BD_O(0));    // 128*64 floats = 32 KB
    float* rsred = (float*)(smr + UK_O(0));    // 128 floats
    const int rl0 = wm + gq, rl1 = rl0 + 8;
    if (jh == 1){
        if (tq == 0){ rsred[rl0] = rs_0; rsred[rl1] = rs_1; }
        #pragma unroll
        for (int ni=0;ni<8;ni++){
            const int d = ni*8 + 2*tq;
            *(float2*)&pvred[rl0*64 + d] = make_float2(acc_pv[ni][0], acc_pv[ni][1]);
            *(float2*)&pvred[rl1*64 + d] = make_float2(acc_pv[ni][2], acc_pv[ni][3]);
        }
    }
    __syncthreads();
    if (jh == 0){
        const float t0 = rs_0 + rsred[rl0];
        const float t1 = rs_1 + rsred[rl1];
        if (tq == 0){
            g_rs[gg*LQ + i0 + rl0] = t0;
            g_rs[gg*LQ + i0 + rl1] = t1;
        }
        const float inv0 = 1.f / t0, inv1 = 1.f / t1;
        const int b = gg >> 4, h = gg & (NH-1);
        __half* dst0 = g_av + (size_t)((i0+rl0)*BATCH + b)*DMODEL + (h<<6);
        __half* dst1 = g_av + (size_t)((i0+rl1)*BATCH + b)*DMODEL + (h<<6);
        #pragma unroll
        for (int ni=0;ni<8;ni++){
            const int d = ni*8 + 2*tq;
            float2 o0 = *(float2*)&pvred[rl0*64 + d];
            float2 o1 = *(float2*)&pvred[rl1*64 + d];
            *reinterpret_cast<unsigned*>(dst0 + d) =
                pack_h2((acc_pv[ni][0]+o0.x)*inv0, (acc_pv[ni][1]+o0.y)*inv0);
            *reinterpret_cast<unsigned*>(dst1 + d) =
                pack_h2((acc_pv[ni][2]+o1.x)*inv1, (acc_pv[ni][3]+o1.y)*inv1);
        }
    }
}

// ---------------- attn_matrix = mean over (b,h) of p/rs --------------------------
__global__ __launch_bounds__(256) void attnmat_kernel(float* __restrict__ out)
{
    const int i  = blockIdx.y;
    const int j0 = blockIdx.x << 9;
    const int jmax = i + MEMLEN;
    const int tid = threadIdx.x;
    const int jq = tid & 63;
    const int gsel = tid >> 6;
    const int j = j0 + jq*8;
    __shared__ float red[256][9];

    float a[8] = {0.f,0.f,0.f,0.f,0.f,0.f,0.f,0.f};
    if (j0 <= jmax){
        #pragma unroll
        for (int gi=0; gi<8; gi++){
            int g = gsel*8 + gi;
            float inv = 1.f / g_rs[g*LQ + i];
            uint4 raw = *(const uint4*)(g_p + ((size_t)g*LQ + i)*TT + j);
            const __half2* hp = (const __half2*)&raw;
            #pragma unroll
            for (int e=0;e<4;e++){
                float2 f = __half22float2(hp[e]);
                a[2*e]   += f.x * inv;
                a[2*e+1] += f.y * inv;
            }
        }
        #pragma unroll
        for (int e=0;e<8;e++) if (j+e > jmax) a[e] = 0.f;
    }
    #pragma unroll
    for (int e=0;e<8;e++) red[tid][e] = a[e];
    __syncthreads();
    if (tid < 64){
        const float k = 1.f/NG;
        float o[8];
        #pragma unroll
        for (int e=0;e<8;e++)
            o[e] = (red[tid][e] + red[tid+64][e] + red[tid+128][e] + red[tid+192][e]) * k;
        float* dst = out + (size_t)i*TT + j0 + tid*8;
        *(float4*)dst     = make_float4(o[0],o[1],o[2],o[3]);
        *(float4*)(dst+4) = make_float4(o[4],o[5],o[6],o[7]);
    }
}

// ---------------- Wo GEMM + residual (fp16 MMA): g_h = x + g_av @ Wo ------------
__global__ __launch_bounds__(256) void wo_mma(const float* __restrict__ x)
{
    const int m0 = blockIdx.y << 7;
    const int n0 = blockIdx.x << 6;

    __shared__ __half   As[128*40];
    __shared__ unsigned Bs[16*72];

    const int tid = threadIdx.x;
    const int warp = tid >> 5, lane = tid & 31;
    const int gq = lane >> 2, tq = lane & 3;
    const int wm = (warp >> 1) * 32, wn = (warp & 1) * 32;
    const unsigned* As2 = (const unsigned*)As;

    float acc[2][4][4];
    #pragma unroll
    for (int mi=0;mi<2;mi++)
        #pragma unroll
        for (int ni=0;ni<4;ni++)
            #pragma unroll
            for (int c=0;c<4;c++) acc[mi][ni][c]=0.f;

    const int a_r = tid >> 1;
    const int a_cb = (tid & 1) * 16;
    const __half* arow = g_av + (size_t)(m0 + a_r)*DMODEL + a_cb;
    const int b_k2 = tid >> 4;
    const int b_cb = (tid & 15) * 4;

    for (int k0=0;k0<DMODEL;k0+=32){
        {
            __half* Ad = As + a_r*40 + a_cb;
            *(uint4*)Ad     = *(const uint4*)(arow + k0);
            *(uint4*)(Ad+8) = *(const uint4*)(arow + k0 + 8);
            const unsigned* bsrc = g_woi + (size_t)((k0>>1) + b_k2)*DMODEL + n0 + b_cb;
            *(uint4*)&Bs[b_k2*72 + b_cb] = *(const uint4*)bsrc;
        }
        __syncthreads();
        #pragma unroll
        for (int kk=0;kk<32;kk+=16){
            const int k2 = kk >> 1;
            unsigned a[2][4], bfr[4][2];
            #pragma unroll
            for (int mi=0;mi<2;mi++){
                int m = wm + mi*16;
                a[mi][0] = As2[(m+gq  )*20 + k2 + tq  ];
                a[mi][1] = As2[(m+gq+8)*20 + k2 + tq  ];
                a[mi][2] = As2[(m+gq  )*20 + k2 + tq+4];
                a[mi][3] = As2[(m+gq+8)*20 + k2 + tq+4];
            }
            #pragma unroll
            for (int ni=0;ni<4;ni++){
                int n = wn + ni*8 + gq;
                bfr[ni][0] = Bs[(k2+tq  )*72 + n];
                bfr[ni][1] = Bs[(k2+tq+4)*72 + n];
            }
            #pragma unroll
            for (int mi=0;mi<2;mi++)
                #pragma unroll
                for (int ni=0;ni<4;ni++)
                    mma_f16(acc[mi][ni], a[mi][0],a[mi][1],a[mi][2],a[mi][3], bfr[ni][0],bfr[ni][1]);
        }
        __syncthreads();
    }

    #pragma unroll
    for (int mi=0;mi<2;mi++)
        #pragma unroll
        for (int rr=0;rr<2;rr++){
            const int row = m0 + wm + mi*16 + gq + rr*8;
            #pragma unroll
            for (int ni=0;ni<4;ni++){
                const int col = n0 + wn + ni*8 + 2*tq;
                float2 xv = *(const float2*)&x[(size_t)row*DMODEL + col];
                float2 val = { acc[mi][ni][rr*2+0] + xv.x,
                               acc[mi][ni][rr*2+1] + xv.y };
                *(float2*)&g_h[(size_t)row*DMODEL + col] = val;
            }
        }
}

// ---------------- layernorm ------------------------------------------------------
__global__ __launch_bounds__(256) void ln_kernel(const float* __restrict__ gamma,
                                                 const float* __restrict__ beta,
                                                 float* __restrict__ out)
{
    const int row = blockIdx.x;
    const float* hr = g_h + (size_t)row*DMODEL;
    const int c = threadIdx.x * 4;
    float4 v = *(const float4*)(hr + c);
    float s = v.x+v.y+v.z+v.w;
    s = blockSum(s);
    const float mu = s * (1.f/DMODEL);
    float dx = v.x-mu, dy = v.y-mu, dz = v.z-mu, dw = v.w-mu;
    float sq = dx*dx+dy*dy+dz*dz+dw*dw;
    sq = blockSum(sq);
    const float inv = rsqrtf(sq*(1.f/DMODEL) + 1e-5f);
    float4 gm = *(const float4*)(gamma + c);
    float4 bt = *(const float4*)(beta + c);
    float4 o;
    o.x = dx*inv*gm.x + bt.x;
    o.y = dy*inv*gm.y + bt.y;
    o.z = dz*inv*gm.z + bt.z;
    o.w = dw*inv*gm.w + bt.w;
    *(float4*)(out + (size_t)row*DMODEL + c) = o;
}

// ---------------- launch ----------------------------------------------------------
extern "C" void kernel_launch(void* const* d_in, const int* in_sizes, int n_in,
                              void* d_out, int out_size)
{
    const float* x        = (const float*)d_in[0];
    const float* pos_emb  = (const float*)d_in[1];
    const float* memory   = (const float*)d_in[2];
    const float* ubias    = (const float*)d_in[3];
    const float* vbias    = (const float*)d_in[4];
    const float* Wq       = (const float*)d_in[6];
    const float* Wkv      = (const float*)d_in[7];
    const float* Wrel     = (const float*)d_in[8];
    const float* Wo       = (const float*)d_in[9];
    const float* gamma    = (const float*)d_in[10];
    const float* beta     = (const float*)d_in[11];
    float* out    = (float*)d_out;
    float* out_am = out + (size_t)LQ*BATCH*DMODEL;

    cudaFuncSetAttribute(flash_mma, cudaFuncAttributeMaxDynamicSharedMemorySize, FL_SMEM_BYTES);
    cudaFuncSetAttribute(qkvr_mma,  cudaFuncAttributeMaxDynamicSharedMemorySize, QK_SMEM_BYTES);

    cvt_all<<<5632, 256>>>(x, memory, pos_emb, Wq, Wkv, Wrel, Wo);
    qkvr_mma<<<896, 256, QK_SMEM_BYTES>>>();
    ukvr_kernel<<<dim3(TT/32, NG), 256>>>(ubias, vbias);
    flash_mma<<<dim3(8, NG), 512, FL_SMEM_BYTES>>>();
    attnmat_kernel<<<dim3(4, LQ), 256>>>(out_am);
    wo_mma<<<dim3(16,16), 256>>>(x);
    ln_kernel<<<LQ*BATCH, 256>>>(gamma, beta, out);
}